// round 1
// baseline (speedup 1.0000x reference)
#include <cuda_runtime.h>
#include <math.h>

// Problem constants
#define BATCH 32
#define SEQL  2048
#define EDIM  512
#define HDIM  512
#define MTOT  (BATCH * SEQL)   // 65536

// Scratch: h = tanh(enc @ W_h + b) [MTOT, HDIM]; att = h @ W_c [MTOT, EDIM]
__device__ float g_h[(size_t)MTOT * HDIM];
__device__ float g_att[(size_t)MTOT * EDIM];

// ---------------------------------------------------------------------------
// Tiled SGEMM: C[M,N] = A[M,K] @ W[K,N] (+ bias, tanh if TANH)
// Block tile 128x128, K-step 8, 256 threads (16x16), 8x8 per thread.
// M=65536, N=512, K=512 -> all tile-divisible, no bounds checks.
// ---------------------------------------------------------------------------
template <bool TANH>
__global__ __launch_bounds__(256) void sgemm_kernel(
    const float* __restrict__ A, const float* __restrict__ W,
    const float* __restrict__ bias, float* __restrict__ C,
    int M, int N, int K)
{
    __shared__ float As[8][128];  // transposed A tile: As[k][m]
    __shared__ float Bs[8][128];  // Bs[k][n]

    const int tx  = threadIdx.x;        // 0..15
    const int ty  = threadIdx.y;        // 0..15
    const int tid = ty * 16 + tx;       // 0..255

    const int bm = blockIdx.y * 128;
    const int bn = blockIdx.x * 128;

    // Global->shared load mapping
    const int ar = tid >> 1;            // A tile row   0..127
    const int ac = (tid & 1) * 4;       // A tile k-col 0 or 4
    const int br = tid >> 5;            // B tile k-row 0..7
    const int bc = (tid & 31) * 4;      // B tile col   0..124

    float acc[8][8];
    #pragma unroll
    for (int i = 0; i < 8; i++)
        #pragma unroll
        for (int j = 0; j < 8; j++) acc[i][j] = 0.0f;

    const float* Aptr = A + (size_t)(bm + ar) * K + ac;
    const float* Wptr = W + (size_t)br * N + bn + bc;

    for (int k0 = 0; k0 < K; k0 += 8) {
        float4 av = *reinterpret_cast<const float4*>(Aptr + k0);
        As[ac + 0][ar] = av.x;
        As[ac + 1][ar] = av.y;
        As[ac + 2][ar] = av.z;
        As[ac + 3][ar] = av.w;
        float4 bv = *reinterpret_cast<const float4*>(Wptr + (size_t)k0 * N);
        *reinterpret_cast<float4*>(&Bs[br][bc]) = bv;
        __syncthreads();

        #pragma unroll
        for (int k = 0; k < 8; k++) {
            float4 a_lo = *reinterpret_cast<float4*>(&As[k][ty * 4]);
            float4 a_hi = *reinterpret_cast<float4*>(&As[k][64 + ty * 4]);
            float4 b_lo = *reinterpret_cast<float4*>(&Bs[k][tx * 4]);
            float4 b_hi = *reinterpret_cast<float4*>(&Bs[k][64 + tx * 4]);
            float a[8] = {a_lo.x, a_lo.y, a_lo.z, a_lo.w,
                          a_hi.x, a_hi.y, a_hi.z, a_hi.w};
            float b[8] = {b_lo.x, b_lo.y, b_lo.z, b_lo.w,
                          b_hi.x, b_hi.y, b_hi.z, b_hi.w};
            #pragma unroll
            for (int i = 0; i < 8; i++)
                #pragma unroll
                for (int j = 0; j < 8; j++)
                    acc[i][j] = fmaf(a[i], b[j], acc[i][j]);
        }
        __syncthreads();
    }

    // Epilogue: rows = bm + ty*4 + (i&3) + (i>>2)*64, cols analogous.
    #pragma unroll
    for (int i = 0; i < 8; i++) {
        int row = bm + ty * 4 + (i & 3) + (i >> 2) * 64;
        #pragma unroll
        for (int jh = 0; jh < 2; jh++) {           // two float4 col groups
            int col = bn + jh * 64 + tx * 4;
            float4 v;
            v.x = acc[i][jh * 4 + 0];
            v.y = acc[i][jh * 4 + 1];
            v.z = acc[i][jh * 4 + 2];
            v.w = acc[i][jh * 4 + 3];
            if (TANH) {
                v.x = tanhf(v.x + bias[col + 0]);
                v.y = tanhf(v.y + bias[col + 1]);
                v.z = tanhf(v.z + bias[col + 2]);
                v.w = tanhf(v.w + bias[col + 3]);
            }
            *reinterpret_cast<float4*>(&C[(size_t)row * N + col]) = v;
        }
    }
}

// ---------------------------------------------------------------------------
// Fused masked softmax over L (per batch, per feature) + weighted sum.
// One block per batch, thread e owns feature column e. Fully coalesced:
// for a fixed l the 512 threads read 512 contiguous floats.
// Branchless online softmax (running max / sum / weighted accumulator).
// ---------------------------------------------------------------------------
__global__ __launch_bounds__(512) void softmax_wsum_kernel(
    const float* __restrict__ att, const float* __restrict__ enc,
    const int* __restrict__ lengths, float* __restrict__ out)
{
    const int b = blockIdx.x;
    const int e = threadIdx.x;
    const int len = lengths[b];

    const float* attb = att + (size_t)b * SEQL * EDIM + e;
    const float* encb = enc + (size_t)b * SEQL * EDIM + e;

    float m = -INFINITY;
    float s = 0.0f;
    float acc = 0.0f;

    for (int l = 0; l < len; l++) {
        float x = attb[(size_t)l * EDIM];
        float v = encb[(size_t)l * EDIM];
        float mn   = fmaxf(m, x);
        float corr = __expf(m - mn);   // first iter: exp(-inf) = 0
        float p    = __expf(x - mn);
        s   = s * corr + p;
        acc = acc * corr + p * v;
        m = mn;
    }
    out[(size_t)b * EDIM + e] = acc / s;
}

// ---------------------------------------------------------------------------
// Inputs (metadata order): encodings [B,L,E] f32, lengths [B] i32,
//                          W_h [E,H] f32, b_h [H] f32, W_c [H,E] f32.
// Output: [B,1,E] f32 = 16384 floats.
// ---------------------------------------------------------------------------
extern "C" void kernel_launch(void* const* d_in, const int* in_sizes, int n_in,
                              void* d_out, int out_size)
{
    const float* enc  = (const float*)d_in[0];
    const int*   len  = (const int*)  d_in[1];
    const float* W_h  = (const float*)d_in[2];
    const float* b_h  = (const float*)d_in[3];
    const float* W_c  = (const float*)d_in[4];
    float* out = (float*)d_out;

    float* h_buf;
    float* att_buf;
    cudaGetSymbolAddress((void**)&h_buf,   g_h);
    cudaGetSymbolAddress((void**)&att_buf, g_att);

    dim3 block(16, 16);
    dim3 grid(HDIM / 128, MTOT / 128);   // (4, 512)

    // h = tanh(enc @ W_h + b_h)
    sgemm_kernel<true><<<grid, block>>>(enc, W_h, b_h, h_buf, MTOT, HDIM, EDIM);
    // att = h @ W_c
    sgemm_kernel<false><<<grid, block>>>(h_buf, W_c, nullptr, att_buf, MTOT, EDIM, HDIM);
    // masked softmax over L + weighted sum
    softmax_wsum_kernel<<<BATCH, EDIM>>>(att_buf, enc, len, out);
}

// round 3
// speedup vs baseline: 2.5552x; 2.5552x over previous
#include <cuda_runtime.h>
#include <cuda_bf16.h>
#include <math.h>
#include <stdint.h>

// Problem constants
#define BATCH 32
#define SEQL  2048
#define EDIM  512
#define HDIM  512
#define KDIM  512
#define MTOT  (BATCH * SEQL)     // 65536
#define NCH   32                 // softmax L-chunks
#define LCH   (SEQL / NCH)       // 64
#define ROWE  1024               // bf16 elems per row in HL layout: (512/32)*64

// HL layout: row r, k: offset = r*1024 + (k/32)*64 + part*32 + (k%32)
__device__ __nv_bfloat16 g_encHL[(size_t)MTOT * ROWE];
__device__ __nv_bfloat16 g_hHL  [(size_t)MTOT * ROWE];
__device__ __nv_bfloat16 g_WhHL [(size_t)HDIM * ROWE];   // B operand: [n][k...]
__device__ __nv_bfloat16 g_WcHL [(size_t)EDIM * ROWE];
__device__ float g_att[(size_t)MTOT * EDIM];
__device__ float g_pm [BATCH * NCH * EDIM];
__device__ float g_ps [BATCH * NCH * EDIM];
__device__ float g_pa [BATCH * NCH * EDIM];

// ---------------------------------------------------------------------------
// helpers
// ---------------------------------------------------------------------------
__device__ __forceinline__ uint32_t s2u(const void* p) {
    uint32_t a;
    asm("{ .reg .u64 t; cvta.to.shared.u64 t, %1; cvt.u32.u64 %0, t; }"
        : "=r"(a) : "l"(p));
    return a;
}
__device__ __forceinline__ void cp16(uint32_t dst, const void* src) {
    asm volatile("cp.async.cg.shared.global [%0], [%1], 16;"
                 :: "r"(dst), "l"(src) : "memory");
}
__device__ __forceinline__ void ldsm4(uint32_t* r, uint32_t addr) {
    asm volatile("ldmatrix.sync.aligned.m8n8.x4.shared.b16 {%0,%1,%2,%3}, [%4];"
                 : "=r"(r[0]), "=r"(r[1]), "=r"(r[2]), "=r"(r[3]) : "r"(addr));
}
__device__ __forceinline__ void mma16816(float* d, const uint32_t* a,
                                         const uint32_t* b) {
    asm volatile(
        "mma.sync.aligned.m16n8k16.row.col.f32.bf16.bf16.f32 "
        "{%0,%1,%2,%3},{%4,%5,%6,%7},{%8,%9},{%0,%1,%2,%3};"
        : "+f"(d[0]), "+f"(d[1]), "+f"(d[2]), "+f"(d[3])
        : "r"(a[0]), "r"(a[1]), "r"(a[2]), "r"(a[3]), "r"(b[0]), "r"(b[1]));
}
__device__ __forceinline__ void split_bf16(float v, __nv_bfloat16& h,
                                           __nv_bfloat16& l) {
    h = __float2bfloat16(v);
    l = __float2bfloat16(v - __bfloat162float(h));
}

// ---------------------------------------------------------------------------
// convert encodings fp32 [M][512] -> HL layout. one thread = 4 k's of one row.
// ---------------------------------------------------------------------------
__global__ __launch_bounds__(256) void convert_A(
    const float* __restrict__ src, __nv_bfloat16* __restrict__ dst)
{
    const size_t g = (size_t)blockIdx.x * 256 + threadIdx.x;   // M*128 threads
    const int m  = (int)(g >> 7);
    const int kq = (int)(g & 127);
    const int k  = kq * 4;
    float4 v = *reinterpret_cast<const float4*>(src + (size_t)m * KDIM + k);
    __nv_bfloat16 h[4], l[4];
    split_bf16(v.x, h[0], l[0]);
    split_bf16(v.y, h[1], l[1]);
    split_bf16(v.z, h[2], l[2]);
    split_bf16(v.w, h[3], l[3]);
    __nv_bfloat16* p = dst + (size_t)m * ROWE + (k >> 5) * 64 + (k & 31);
    *reinterpret_cast<uint2*>(p)      = *reinterpret_cast<uint2*>(h);
    *reinterpret_cast<uint2*>(p + 32) = *reinterpret_cast<uint2*>(l);
}

// ---------------------------------------------------------------------------
// convert W fp32 [K][N] -> N-major HL layout [n][k...]. 512x512, tiny.
// ---------------------------------------------------------------------------
__global__ __launch_bounds__(256) void convert_W(
    const float* __restrict__ W, __nv_bfloat16* __restrict__ dst)
{
    const int g = blockIdx.x * 256 + threadIdx.x;   // 512*512 threads
    const int k = g >> 9;
    const int n = g & 511;
    __nv_bfloat16 h, l;
    split_bf16(W[(size_t)k * 512 + n], h, l);
    __nv_bfloat16* p = dst + (size_t)n * ROWE + (k >> 5) * 64 + (k & 31);
    p[0]  = h;
    p[32] = l;
}

// ---------------------------------------------------------------------------
// bf16x3 tensor-core GEMM: C[M,N] = A[M,512] @ B (+bias,tanh).
// A, B in HL layout. CTA tile 128x128, 8 warps (2m x 4n), warp 64x32.
// k-chunk 32 per stage, double-buffered cp.async, swizzled smem.
// TANH: writes h as HL bf16; else writes fp32 C.
// smem/stage: A 128x128B = 16KB, B 16KB; 2 stages = 64KB dynamic.
// ---------------------------------------------------------------------------
#define GEMM_SMEM (2 * 32768)

template <bool TANH>
__global__ void __launch_bounds__(256) gemm_bf16x3(
    const __nv_bfloat16* __restrict__ A, const __nv_bfloat16* __restrict__ Bm,
    const float* __restrict__ bias, float* __restrict__ Cf,
    __nv_bfloat16* __restrict__ Chl)
{
    extern __shared__ char smem[];
    const uint32_t sbase = s2u(smem);
    const int tid  = threadIdx.x;
    const int wid  = tid >> 5, lane = tid & 31;
    const int bm = blockIdx.y * 128, bn = blockIdx.x * 128;
    const int wm = (wid >> 2) * 64, wn = (wid & 3) * 32;

    const __nv_bfloat16* Abase = A  + (size_t)bm * ROWE;
    const __nv_bfloat16* Bbase = Bm + (size_t)bn * ROWE;

    float acc[4][4][4];
    #pragma unroll
    for (int i = 0; i < 4; i++)
        #pragma unroll
        for (int j = 0; j < 4; j++)
            #pragma unroll
            for (int q = 0; q < 4; q++) acc[i][j][q] = 0.0f;

    // per-thread copy slots: ids tid+i*256 -> row=id/8, chunk=id%8
    const int cr = tid >> 3;          // base row (row for i via +32*i)
    const int cc = tid & 7;           // chunk

    auto load_stage = [&](int kc, int buf) {
        const uint32_t sA = sbase + buf * 32768;
        const uint32_t sB = sA + 16384;
        #pragma unroll
        for (int i = 0; i < 4; i++) {
            const int r = cr + i * 32;
            const uint32_t off = (uint32_t)(r * 128 + ((cc ^ (r & 7)) << 4));
            cp16(sA + off, Abase + (size_t)r * ROWE + kc * 64 + cc * 8);
            cp16(sB + off, Bbase + (size_t)r * ROWE + kc * 64 + cc * 8);
        }
        asm volatile("cp.async.commit_group;" ::: "memory");
    };

    auto compute_stage = [&](int buf) {
        const uint32_t sA = sbase + buf * 32768;
        const uint32_t sB = sA + 16384;
        #pragma unroll
        for (int pass = 0; pass < 3; pass++) {
            const int pa = (pass == 2) ? 1 : 0;   // A part: hi,hi,lo
            const int pb = (pass == 1) ? 1 : 0;   // B part: hi,lo,hi
            #pragma unroll
            for (int s = 0; s < 2; s++) {
                uint32_t a[4][4];
                #pragma unroll
                for (int mt = 0; mt < 4; mt++) {
                    const int r = wm + mt * 16 + (lane & 7) + ((lane >> 3) & 1) * 8;
                    const int c = pa * 4 + s * 2 + (lane >> 4);
                    ldsm4(a[mt], sA + r * 128 + ((c ^ (r & 7)) << 4));
                }
                uint32_t b[4][2];
                #pragma unroll
                for (int np = 0; np < 2; np++) {
                    const int r = wn + np * 16 + (lane & 7) + ((lane >> 4) & 1) * 8;
                    const int c = pb * 4 + s * 2 + ((lane >> 3) & 1);
                    uint32_t t[4];
                    ldsm4(t, sB + r * 128 + ((c ^ (r & 7)) << 4));
                    b[np * 2 + 0][0] = t[0]; b[np * 2 + 0][1] = t[1];
                    b[np * 2 + 1][0] = t[2]; b[np * 2 + 1][1] = t[3];
                }
                #pragma unroll
                for (int mt = 0; mt < 4; mt++)
                    #pragma unroll
                    for (int nt = 0; nt < 4; nt++)
                        mma16816(acc[mt][nt], a[mt], b[nt]);
            }
        }
    };

    load_stage(0, 0);
    #pragma unroll 1
    for (int kc = 0; kc < 16; kc++) {
        if (kc < 15) {
            load_stage(kc + 1, (kc + 1) & 1);
            asm volatile("cp.async.wait_group 1;" ::: "memory");
        } else {
            asm volatile("cp.async.wait_group 0;" ::: "memory");
        }
        __syncthreads();
        compute_stage(kc & 1);
        __syncthreads();
    }

    // Epilogue
    const int gp = lane >> 2, tg = lane & 3;
    #pragma unroll
    for (int mt = 0; mt < 4; mt++) {
        const int m0 = bm + wm + mt * 16 + gp;
        #pragma unroll
        for (int nt = 0; nt < 4; nt++) {
            const int n = bn + wn + nt * 8 + tg * 2;
            float d0 = acc[mt][nt][0], d1 = acc[mt][nt][1];
            float d2 = acc[mt][nt][2], d3 = acc[mt][nt][3];
            if (TANH) {
                const float b0 = __ldg(bias + n), b1 = __ldg(bias + n + 1);
                d0 = tanhf(d0 + b0); d1 = tanhf(d1 + b1);
                d2 = tanhf(d2 + b0); d3 = tanhf(d3 + b1);
                __nv_bfloat16 h0, l0, h1, l1;
                // row m0
                split_bf16(d0, h0, l0); split_bf16(d1, h1, l1);
                __nv_bfloat16* p = Chl + (size_t)m0 * ROWE + (n >> 5) * 64 + (n & 31);
                __nv_bfloat162 hp, lp;
                hp.x = h0; hp.y = h1; lp.x = l0; lp.y = l1;
                *reinterpret_cast<__nv_bfloat162*>(p)      = hp;
                *reinterpret_cast<__nv_bfloat162*>(p + 32) = lp;
                // row m0+8
                split_bf16(d2, h0, l0); split_bf16(d3, h1, l1);
                p += (size_t)8 * ROWE;
                hp.x = h0; hp.y = h1; lp.x = l0; lp.y = l1;
                *reinterpret_cast<__nv_bfloat162*>(p)      = hp;
                *reinterpret_cast<__nv_bfloat162*>(p + 32) = lp;
            } else {
                float2 v0; v0.x = d0; v0.y = d1;
                float2 v1; v1.x = d2; v1.y = d3;
                *reinterpret_cast<float2*>(Cf + (size_t)m0 * EDIM + n)       = v0;
                *reinterpret_cast<float2*>(Cf + (size_t)(m0 + 8) * EDIM + n) = v1;
            }
        }
    }
}

// ---------------------------------------------------------------------------
// Softmax pass 1: per (batch, L-chunk) online-softmax partials per feature.
// ---------------------------------------------------------------------------
__global__ __launch_bounds__(512) void softmax_part(
    const float* __restrict__ att, const float* __restrict__ enc,
    const int* __restrict__ lengths,
    float* __restrict__ pm, float* __restrict__ ps, float* __restrict__ pa)
{
    const int b = blockIdx.y, c = blockIdx.x, e = threadIdx.x;
    const int len = lengths[b];
    const int l0 = c * LCH;
    const int l1 = min(l0 + LCH, len);

    const float* ap = att + ((size_t)b * SEQL + l0) * EDIM + e;
    const float* ep = enc + ((size_t)b * SEQL + l0) * EDIM + e;

    float m = -INFINITY, s = 0.0f, acc = 0.0f;
    for (int l = l0; l < l1; l++) {
        float x = *ap; float v = *ep;
        ap += EDIM; ep += EDIM;
        float mn   = fmaxf(m, x);
        float corr = __expf(m - mn);
        float p    = __expf(x - mn);
        s   = s * corr + p;
        acc = acc * corr + p * v;
        m = mn;
    }
    const size_t o = ((size_t)b * NCH + c) * EDIM + e;
    pm[o] = m; ps[o] = s; pa[o] = acc;
}

__global__ __launch_bounds__(512) void softmax_merge(
    const float* __restrict__ pm, const float* __restrict__ ps,
    const float* __restrict__ pa, float* __restrict__ out)
{
    const int b = blockIdx.x, e = threadIdx.x;
    float M = -INFINITY;
    #pragma unroll 4
    for (int c = 0; c < NCH; c++)
        M = fmaxf(M, pm[((size_t)b * NCH + c) * EDIM + e]);
    float S = 0.0f, Acc = 0.0f;
    #pragma unroll 4
    for (int c = 0; c < NCH; c++) {
        const size_t o = ((size_t)b * NCH + c) * EDIM + e;
        const float w = __expf(pm[o] - M);
        S   += ps[o] * w;
        Acc += pa[o] * w;
    }
    out[(size_t)b * EDIM + e] = Acc / S;
}

// ---------------------------------------------------------------------------
// Inputs: encodings [B,L,E] f32, lengths [B] i32, W_h [E,H] f32,
//         b_h [H] f32, W_c [H,E] f32. Output: [B,1,E] f32.
// ---------------------------------------------------------------------------
extern "C" void kernel_launch(void* const* d_in, const int* in_sizes, int n_in,
                              void* d_out, int out_size)
{
    const float* enc = (const float*)d_in[0];
    const int*   len = (const int*)  d_in[1];
    const float* W_h = (const float*)d_in[2];
    const float* b_h = (const float*)d_in[3];
    const float* W_c = (const float*)d_in[4];
    float* out = (float*)d_out;

    __nv_bfloat16 *encHL, *hHL, *WhHL, *WcHL;
    float *att, *pm, *ps, *pa;
    cudaGetSymbolAddress((void**)&encHL, g_encHL);
    cudaGetSymbolAddress((void**)&hHL,   g_hHL);
    cudaGetSymbolAddress((void**)&WhHL,  g_WhHL);
    cudaGetSymbolAddress((void**)&WcHL,  g_WcHL);
    cudaGetSymbolAddress((void**)&att,   g_att);
    cudaGetSymbolAddress((void**)&pm,    g_pm);
    cudaGetSymbolAddress((void**)&ps,    g_ps);
    cudaGetSymbolAddress((void**)&pa,    g_pa);

    // (unconditional each call — deterministic, host-side only)
    cudaFuncSetAttribute(gemm_bf16x3<true>,
        cudaFuncAttributeMaxDynamicSharedMemorySize, GEMM_SMEM);
    cudaFuncSetAttribute(gemm_bf16x3<false>,
        cudaFuncAttributeMaxDynamicSharedMemorySize, GEMM_SMEM);

    convert_A<<<(MTOT * 128) / 256, 256>>>(enc, encHL);
    convert_W<<<(512 * 512) / 256, 256>>>(W_h, WhHL);
    convert_W<<<(512 * 512) / 256, 256>>>(W_c, WcHL);

    dim3 gg(4, MTOT / 128);   // (N/128, M/128)
    gemm_bf16x3<true ><<<gg, 256, GEMM_SMEM>>>(encHL, WhHL, b_h, nullptr, hHL);
    gemm_bf16x3<false><<<gg, 256, GEMM_SMEM>>>(hHL,   WcHL, nullptr, att, nullptr);

    dim3 gs(NCH, BATCH);
    softmax_part<<<gs, EDIM>>>(att, enc, len, pm, ps, pa);
    softmax_merge<<<BATCH, EDIM>>>(pm, ps, pa, out);
}

// round 4
// speedup vs baseline: 2.8963x; 1.1335x over previous
#include <cuda_runtime.h>
#include <cuda_bf16.h>
#include <math.h>
#include <stdint.h>

// Problem constants
#define BATCH 32
#define SEQL  2048
#define EDIM  512
#define HDIM  512
#define KDIM  512
#define MTOT  (BATCH * SEQL)     // 65536
#define NCH   32                 // softmax L-chunks
#define LCH   (SEQL / NCH)       // 64
#define ROWE  1024               // bf16 elems per row in HL layout: (512/32)*64

// HL layout: row r, k: offset = r*1024 + (k/32)*64 + part*32 + (k%32)
__device__ __nv_bfloat16 g_encHL[(size_t)MTOT * ROWE];
__device__ __nv_bfloat16 g_hHL  [(size_t)MTOT * ROWE];
__device__ __nv_bfloat16 g_WhHL [(size_t)HDIM * ROWE];   // B operand: [n][k...]
__device__ __nv_bfloat16 g_WcHL [(size_t)EDIM * ROWE];
__device__ float g_att[(size_t)MTOT * EDIM];
__device__ float g_pm [BATCH * NCH * EDIM];
__device__ float g_ps [BATCH * NCH * EDIM];
__device__ float g_pa [BATCH * NCH * EDIM];

// ---------------------------------------------------------------------------
// helpers
// ---------------------------------------------------------------------------
__device__ __forceinline__ uint32_t s2u(const void* p) {
    uint32_t a;
    asm("{ .reg .u64 t; cvta.to.shared.u64 t, %1; cvt.u32.u64 %0, t; }"
        : "=r"(a) : "l"(p));
    return a;
}
__device__ __forceinline__ void cp16(uint32_t dst, const void* src) {
    asm volatile("cp.async.cg.shared.global [%0], [%1], 16;"
                 :: "r"(dst), "l"(src) : "memory");
}
__device__ __forceinline__ void ldsm4(uint32_t* r, uint32_t addr) {
    asm volatile("ldmatrix.sync.aligned.m8n8.x4.shared.b16 {%0,%1,%2,%3}, [%4];"
                 : "=r"(r[0]), "=r"(r[1]), "=r"(r[2]), "=r"(r[3]) : "r"(addr));
}
__device__ __forceinline__ void mma16816(float* d, const uint32_t* a,
                                         const uint32_t* b) {
    asm volatile(
        "mma.sync.aligned.m16n8k16.row.col.f32.bf16.bf16.f32 "
        "{%0,%1,%2,%3},{%4,%5,%6,%7},{%8,%9},{%0,%1,%2,%3};"
        : "+f"(d[0]), "+f"(d[1]), "+f"(d[2]), "+f"(d[3])
        : "r"(a[0]), "r"(a[1]), "r"(a[2]), "r"(a[3]), "r"(b[0]), "r"(b[1]));
}
__device__ __forceinline__ void split_bf16(float v, __nv_bfloat16& h,
                                           __nv_bfloat16& l) {
    h = __float2bfloat16(v);
    l = __float2bfloat16(v - __bfloat162float(h));
}

// ---------------------------------------------------------------------------
// convert encodings fp32 [M][512] -> HL layout.
// ---------------------------------------------------------------------------
__global__ __launch_bounds__(256) void convert_A(
    const float* __restrict__ src, __nv_bfloat16* __restrict__ dst)
{
    const size_t g = (size_t)blockIdx.x * 256 + threadIdx.x;   // M*128 threads
    const int m  = (int)(g >> 7);
    const int kq = (int)(g & 127);
    const int k  = kq * 4;
    float4 v = *reinterpret_cast<const float4*>(src + (size_t)m * KDIM + k);
    __nv_bfloat16 h[4], l[4];
    split_bf16(v.x, h[0], l[0]);
    split_bf16(v.y, h[1], l[1]);
    split_bf16(v.z, h[2], l[2]);
    split_bf16(v.w, h[3], l[3]);
    __nv_bfloat16* p = dst + (size_t)m * ROWE + (k >> 5) * 64 + (k & 31);
    *reinterpret_cast<uint2*>(p)      = *reinterpret_cast<uint2*>(h);
    *reinterpret_cast<uint2*>(p + 32) = *reinterpret_cast<uint2*>(l);
}

// ---------------------------------------------------------------------------
// convert W fp32 [K][N] -> N-major HL layout [n][k...].
// ---------------------------------------------------------------------------
__global__ __launch_bounds__(256) void convert_W(
    const float* __restrict__ W, __nv_bfloat16* __restrict__ dst)
{
    const int g = blockIdx.x * 256 + threadIdx.x;   // 512*512 threads
    const int k = g >> 9;
    const int n = g & 511;
    __nv_bfloat16 h, l;
    split_bf16(W[(size_t)k * 512 + n], h, l);
    __nv_bfloat16* p = dst + (size_t)n * ROWE + (k >> 5) * 64 + (k & 31);
    p[0]  = h;
    p[32] = l;
}

// ---------------------------------------------------------------------------
// bf16x3 tensor-core GEMM: C[M,N] = A[M,512] @ B (+bias,tanh).
// CTA tile 128x128, 8 warps (2m x 4n), warp 64x32, k=32/stage.
// 3-stage cp.async pipeline, 1 syncthreads/stage, 2 CTAs/SM.
// Fragment reuse: aH*(bH,bL) + aL*bH -> 24 ldmatrix / 48 mma per stage.
// ---------------------------------------------------------------------------
#define STAGE_BYTES 32768
#define GEMM_SMEM   (3 * STAGE_BYTES)

template <bool TANH>
__global__ void __launch_bounds__(256, 2) gemm_bf16x3(
    const __nv_bfloat16* __restrict__ A, const __nv_bfloat16* __restrict__ Bm,
    const float* __restrict__ bias, float* __restrict__ Cf,
    __nv_bfloat16* __restrict__ Chl)
{
    extern __shared__ char smem[];
    const uint32_t sbase = s2u(smem);
    const int tid  = threadIdx.x;
    const int wid  = tid >> 5, lane = tid & 31;
    const int bm = blockIdx.y * 128, bn = blockIdx.x * 128;
    const int wm = (wid >> 2) * 64, wn = (wid & 3) * 32;

    // ldmatrix per-thread invariants (row&7 == lane&7 for both operands)
    const uint32_t xm   = (uint32_t)(lane & 7);
    const uint32_t rowA = (uint32_t)(wm + (lane & 15)) * 128;
    const uint32_t rowB = (uint32_t)(wn + (lane & 7) + ((lane >> 4) & 1) * 8) * 128;
    const int cA0 = (lane >> 4);         // 0..1
    const int cB0 = ((lane >> 3) & 1);   // 0..1

    float acc[4][4][4];
    #pragma unroll
    for (int i = 0; i < 4; i++)
        #pragma unroll
        for (int j = 0; j < 4; j++)
            #pragma unroll
            for (int q = 0; q < 4; q++) acc[i][j][q] = 0.0f;

    // cp.async per-thread invariants: 256 threads cover 32 rows x 8 chunks
    const int cr = tid >> 3, cc = tid & 7;
    const __nv_bfloat16* Ag = A  + (size_t)(bm + cr) * ROWE + cc * 8;
    const __nv_bfloat16* Bg = Bm + (size_t)(bn + cr) * ROWE + cc * 8;
    const uint32_t soff = (uint32_t)(cr * 128 + ((cc ^ (cr & 7)) << 4));

    auto load_stage = [&](int kc, int buf) {
        const uint32_t sA = sbase + (uint32_t)buf * STAGE_BYTES;
        const uint32_t sB = sA + 16384;
        #pragma unroll
        for (int i = 0; i < 4; i++) {
            cp16(sA + soff + i * 32 * 128, Ag + (size_t)i * 32 * ROWE + kc * 64);
            cp16(sB + soff + i * 32 * 128, Bg + (size_t)i * 32 * ROWE + kc * 64);
        }
    };

    auto compute_stage = [&](int buf) {
        const uint32_t sA = sbase + (uint32_t)buf * STAGE_BYTES;
        const uint32_t sB = sA + 16384;
        #pragma unroll
        for (int s = 0; s < 2; s++) {
            const uint32_t ca = (uint32_t)(s * 2 + cA0);
            const uint32_t cb = (uint32_t)(s * 2 + cB0);
            uint32_t aH[4][4];
            #pragma unroll
            for (int mt = 0; mt < 4; mt++)
                ldsm4(aH[mt], sA + rowA + mt * 2048 + ((ca ^ xm) << 4));
            uint32_t bH[4][2];
            #pragma unroll
            for (int np = 0; np < 2; np++) {
                uint32_t t[4];
                ldsm4(t, sB + rowB + np * 2048 + ((cb ^ xm) << 4));
                bH[np * 2 + 0][0] = t[0]; bH[np * 2 + 0][1] = t[1];
                bH[np * 2 + 1][0] = t[2]; bH[np * 2 + 1][1] = t[3];
            }
            #pragma unroll
            for (int mt = 0; mt < 4; mt++)
                #pragma unroll
                for (int nt = 0; nt < 4; nt++)
                    mma16816(acc[mt][nt], aH[mt], bH[nt]);
            {   // aH * bL
                uint32_t bL[4][2];
                #pragma unroll
                for (int np = 0; np < 2; np++) {
                    uint32_t t[4];
                    ldsm4(t, sB + rowB + np * 2048 + (((cb + 4) ^ xm) << 4));
                    bL[np * 2 + 0][0] = t[0]; bL[np * 2 + 0][1] = t[1];
                    bL[np * 2 + 1][0] = t[2]; bL[np * 2 + 1][1] = t[3];
                }
                #pragma unroll
                for (int mt = 0; mt < 4; mt++)
                    #pragma unroll
                    for (int nt = 0; nt < 4; nt++)
                        mma16816(acc[mt][nt], aH[mt], bL[nt]);
            }
            {   // aL * bH
                uint32_t aL[4][4];
                #pragma unroll
                for (int mt = 0; mt < 4; mt++)
                    ldsm4(aL[mt], sA + rowA + mt * 2048 + (((ca + 4) ^ xm) << 4));
                #pragma unroll
                for (int mt = 0; mt < 4; mt++)
                    #pragma unroll
                    for (int nt = 0; nt < 4; nt++)
                        mma16816(acc[mt][nt], aL[mt], bH[nt]);
            }
        }
    };

    // 3-stage pipeline, one commit per iteration, one sync per iteration.
    load_stage(0, 0);
    asm volatile("cp.async.commit_group;" ::: "memory");
    load_stage(1, 1);
    asm volatile("cp.async.commit_group;" ::: "memory");

    #pragma unroll 1
    for (int kc = 0; kc < 16; kc++) {
        asm volatile("cp.async.wait_group 1;" ::: "memory");
        __syncthreads();            // stage kc visible; stage (kc+2)%3 free
        if (kc + 2 < 16) {
            const int nb = (kc + 2) % 3;
            load_stage(kc + 2, nb);
        }
        asm volatile("cp.async.commit_group;" ::: "memory");
        compute_stage(kc % 3);
    }

    // Epilogue
    const int gp = lane >> 2, tg = lane & 3;
    #pragma unroll
    for (int mt = 0; mt < 4; mt++) {
        const int m0 = bm + wm + mt * 16 + gp;
        #pragma unroll
        for (int nt = 0; nt < 4; nt++) {
            const int n = bn + wn + nt * 8 + tg * 2;
            float d0 = acc[mt][nt][0], d1 = acc[mt][nt][1];
            float d2 = acc[mt][nt][2], d3 = acc[mt][nt][3];
            if (TANH) {
                const float b0 = __ldg(bias + n), b1 = __ldg(bias + n + 1);
                d0 = tanhf(d0 + b0); d1 = tanhf(d1 + b1);
                d2 = tanhf(d2 + b0); d3 = tanhf(d3 + b1);
                __nv_bfloat16 h0, l0, h1, l1;
                split_bf16(d0, h0, l0); split_bf16(d1, h1, l1);
                __nv_bfloat16* p = Chl + (size_t)m0 * ROWE + (n >> 5) * 64 + (n & 31);
                __nv_bfloat162 hp, lp;
                hp.x = h0; hp.y = h1; lp.x = l0; lp.y = l1;
                *reinterpret_cast<__nv_bfloat162*>(p)      = hp;
                *reinterpret_cast<__nv_bfloat162*>(p + 32) = lp;
                split_bf16(d2, h0, l0); split_bf16(d3, h1, l1);
                p += (size_t)8 * ROWE;
                hp.x = h0; hp.y = h1; lp.x = l0; lp.y = l1;
                *reinterpret_cast<__nv_bfloat162*>(p)      = hp;
                *reinterpret_cast<__nv_bfloat162*>(p + 32) = lp;
            } else {
                float2 v0; v0.x = d0; v0.y = d1;
                float2 v1; v1.x = d2; v1.y = d3;
                *reinterpret_cast<float2*>(Cf + (size_t)m0 * EDIM + n)       = v0;
                *reinterpret_cast<float2*>(Cf + (size_t)(m0 + 8) * EDIM + n) = v1;
            }
        }
    }
}

// ---------------------------------------------------------------------------
// Softmax pass 1: per (batch, L-chunk) online-softmax partials per feature.
// ---------------------------------------------------------------------------
__global__ __launch_bounds__(512) void softmax_part(
    const float* __restrict__ att, const float* __restrict__ enc,
    const int* __restrict__ lengths,
    float* __restrict__ pm, float* __restrict__ ps, float* __restrict__ pa)
{
    const int b = blockIdx.y, c = blockIdx.x, e = threadIdx.x;
    const int len = lengths[b];
    const int l0 = c * LCH;
    const int l1 = min(l0 + LCH, len);

    const float* ap = att + ((size_t)b * SEQL + l0) * EDIM + e;
    const float* ep = enc + ((size_t)b * SEQL + l0) * EDIM + e;

    float m = -INFINITY, s = 0.0f, acc = 0.0f;
    for (int l = l0; l < l1; l++) {
        float x = *ap; float v = *ep;
        ap += EDIM; ep += EDIM;
        float mn   = fmaxf(m, x);
        float corr = __expf(m - mn);
        float p    = __expf(x - mn);
        s   = s * corr + p;
        acc = acc * corr + p * v;
        m = mn;
    }
    const size_t o = ((size_t)b * NCH + c) * EDIM + e;
    pm[o] = m; ps[o] = s; pa[o] = acc;
}

__global__ __launch_bounds__(512) void softmax_merge(
    const float* __restrict__ pm, const float* __restrict__ ps,
    const float* __restrict__ pa, float* __restrict__ out)
{
    const int b = blockIdx.x, e = threadIdx.x;
    float M = -INFINITY;
    #pragma unroll 4
    for (int c = 0; c < NCH; c++)
        M = fmaxf(M, pm[((size_t)b * NCH + c) * EDIM + e]);
    float S = 0.0f, Acc = 0.0f;
    #pragma unroll 4
    for (int c = 0; c < NCH; c++) {
        const size_t o = ((size_t)b * NCH + c) * EDIM + e;
        const float w = __expf(pm[o] - M);
        S   += ps[o] * w;
        Acc += pa[o] * w;
    }
    out[(size_t)b * EDIM + e] = Acc / S;
}

// ---------------------------------------------------------------------------
// Inputs: encodings [B,L,E] f32, lengths [B] i32, W_h [E,H] f32,
//         b_h [H] f32, W_c [H,E] f32. Output: [B,1,E] f32.
// ---------------------------------------------------------------------------
extern "C" void kernel_launch(void* const* d_in, const int* in_sizes, int n_in,
                              void* d_out, int out_size)
{
    const float* enc = (const float*)d_in[0];
    const int*   len = (const int*)  d_in[1];
    const float* W_h = (const float*)d_in[2];
    const float* b_h = (const float*)d_in[3];
    const float* W_c = (const float*)d_in[4];
    float* out = (float*)d_out;

    __nv_bfloat16 *encHL, *hHL, *WhHL, *WcHL;
    float *att, *pm, *ps, *pa;
    cudaGetSymbolAddress((void**)&encHL, g_encHL);
    cudaGetSymbolAddress((void**)&hHL,   g_hHL);
    cudaGetSymbolAddress((void**)&WhHL,  g_WhHL);
    cudaGetSymbolAddress((void**)&WcHL,  g_WcHL);
    cudaGetSymbolAddress((void**)&att,   g_att);
    cudaGetSymbolAddress((void**)&pm,    g_pm);
    cudaGetSymbolAddress((void**)&ps,    g_ps);
    cudaGetSymbolAddress((void**)&pa,    g_pa);

    cudaFuncSetAttribute(gemm_bf16x3<true>,
        cudaFuncAttributeMaxDynamicSharedMemorySize, GEMM_SMEM);
    cudaFuncSetAttribute(gemm_bf16x3<false>,
        cudaFuncAttributeMaxDynamicSharedMemorySize, GEMM_SMEM);

    convert_A<<<(MTOT * 128) / 256, 256>>>(enc, encHL);
    convert_W<<<(512 * 512) / 256, 256>>>(W_h, WhHL);
    convert_W<<<(512 * 512) / 256, 256>>>(W_c, WcHL);

    dim3 gg(4, MTOT / 128);   // (N/128, M/128)
    gemm_bf16x3<true ><<<gg, 256, GEMM_SMEM>>>(encHL, WhHL, b_h, nullptr, hHL);
    gemm_bf16x3<false><<<gg, 256, GEMM_SMEM>>>(hHL,   WcHL, nullptr, att, nullptr);

    dim3 gs(NCH, BATCH);
    softmax_part<<<gs, EDIM>>>(att, enc, len, pm, ps, pa);
    softmax_merge<<<BATCH, EDIM>>>(pm, ps, pa, out);
}

// round 5
// speedup vs baseline: 3.3208x; 1.1466x over previous
#include <cuda_runtime.h>
#include <cuda_bf16.h>
#include <math.h>
#include <stdint.h>

// Problem constants
#define BATCH 32
#define SEQL  2048
#define EDIM  512
#define HDIM  512
#define KDIM  512
#define MTOT  (BATCH * SEQL)     // 65536
#define NCH   32                 // softmax L-chunks
#define LCH   (SEQL / NCH)       // 64
#define ROWE  1024               // bf16 elems per row in HL layout: (512/32)*64

// HL layout: row r, k: offset = r*1024 + (k/32)*64 + part*32 + (k%32)
__device__ __nv_bfloat16 g_encHL[(size_t)MTOT * ROWE];
__device__ __nv_bfloat16 g_hHL  [(size_t)MTOT * ROWE];
__device__ __nv_bfloat16 g_WhHL [(size_t)HDIM * ROWE];   // B operand: [n][k...]
__device__ __nv_bfloat16 g_WcHL [(size_t)EDIM * ROWE];
__device__ float g_att[(size_t)MTOT * EDIM];
__device__ float g_pm [BATCH * NCH * EDIM];
__device__ float g_ps [BATCH * NCH * EDIM];
__device__ float g_pa [BATCH * NCH * EDIM];

// ---------------------------------------------------------------------------
// helpers
// ---------------------------------------------------------------------------
__device__ __forceinline__ uint32_t s2u(const void* p) {
    uint32_t a;
    asm("{ .reg .u64 t; cvta.to.shared.u64 t, %1; cvt.u32.u64 %0, t; }"
        : "=r"(a) : "l"(p));
    return a;
}
__device__ __forceinline__ void cp16(uint32_t dst, const void* src) {
    asm volatile("cp.async.cg.shared.global [%0], [%1], 16;"
                 :: "r"(dst), "l"(src) : "memory");
}
__device__ __forceinline__ void ldsm4(uint32_t* r, uint32_t addr) {
    asm volatile("ldmatrix.sync.aligned.m8n8.x4.shared.b16 {%0,%1,%2,%3}, [%4];"
                 : "=r"(r[0]), "=r"(r[1]), "=r"(r[2]), "=r"(r[3]) : "r"(addr));
}
__device__ __forceinline__ void mma16816(float* d, const uint32_t* a,
                                         const uint32_t* b) {
    asm volatile(
        "mma.sync.aligned.m16n8k16.row.col.f32.bf16.bf16.f32 "
        "{%0,%1,%2,%3},{%4,%5,%6,%7},{%8,%9},{%0,%1,%2,%3};"
        : "+f"(d[0]), "+f"(d[1]), "+f"(d[2]), "+f"(d[3])
        : "r"(a[0]), "r"(a[1]), "r"(a[2]), "r"(a[3]), "r"(b[0]), "r"(b[1]));
}
__device__ __forceinline__ void split_bf16(float v, __nv_bfloat16& h,
                                           __nv_bfloat16& l) {
    h = __float2bfloat16(v);
    l = __float2bfloat16(v - __bfloat162float(h));
}
// fast tanh: (e^{2x}-1)/(e^{2x}+1), clamp avoids inf/inf; err ~1e-6.
__device__ __forceinline__ float fast_tanh(float x) {
    x = fminf(fmaxf(x, -15.0f), 15.0f);
    const float e = __expf(2.0f * x);
    return __fdividef(e - 1.0f, e + 1.0f);
}

// ---------------------------------------------------------------------------
// convert encodings fp32 [M][512] -> HL layout.
// ---------------------------------------------------------------------------
__global__ __launch_bounds__(256) void convert_A(
    const float* __restrict__ src, __nv_bfloat16* __restrict__ dst)
{
    const size_t g = (size_t)blockIdx.x * 256 + threadIdx.x;   // M*128 threads
    const int m  = (int)(g >> 7);
    const int kq = (int)(g & 127);
    const int k  = kq * 4;
    float4 v = *reinterpret_cast<const float4*>(src + (size_t)m * KDIM + k);
    __nv_bfloat16 h[4], l[4];
    split_bf16(v.x, h[0], l[0]);
    split_bf16(v.y, h[1], l[1]);
    split_bf16(v.z, h[2], l[2]);
    split_bf16(v.w, h[3], l[3]);
    __nv_bfloat16* p = dst + (size_t)m * ROWE + (k >> 5) * 64 + (k & 31);
    *reinterpret_cast<uint2*>(p)      = *reinterpret_cast<uint2*>(h);
    *reinterpret_cast<uint2*>(p + 32) = *reinterpret_cast<uint2*>(l);
}

// ---------------------------------------------------------------------------
// convert W fp32 [K][N] -> N-major HL layout [n][k...].
// ---------------------------------------------------------------------------
__global__ __launch_bounds__(256) void convert_W(
    const float* __restrict__ W, __nv_bfloat16* __restrict__ dst)
{
    const int g = blockIdx.x * 256 + threadIdx.x;   // 512*512 threads
    const int k = g >> 9;
    const int n = g & 511;
    __nv_bfloat16 h, l;
    split_bf16(W[(size_t)k * 512 + n], h, l);
    __nv_bfloat16* p = dst + (size_t)n * ROWE + (k >> 5) * 64 + (k & 31);
    p[0]  = h;
    p[32] = l;
}

// ---------------------------------------------------------------------------
// bf16x3 tensor-core GEMM: C[M,N] = A[M,512] @ B (+bias,tanh).
// CTA tile 128x128, 8 warps (2m x 4n), warp 64x32, k=32/stage.
// 3-stage cp.async pipeline, fully unrolled k-loop (const-folded addresses),
// 1 syncthreads/stage, 2 CTAs/SM.
// ---------------------------------------------------------------------------
#define STAGE_BYTES 32768
#define GEMM_SMEM   (3 * STAGE_BYTES)

template <bool TANH>
__global__ void __launch_bounds__(256, 2) gemm_bf16x3(
    const __nv_bfloat16* __restrict__ A, const __nv_bfloat16* __restrict__ Bm,
    const float* __restrict__ bias, float* __restrict__ Cf,
    __nv_bfloat16* __restrict__ Chl)
{
    extern __shared__ char smem[];
    const uint32_t sbase = s2u(smem);
    const int tid  = threadIdx.x;
    const int wid  = tid >> 5, lane = tid & 31;
    const int bm = blockIdx.y * 128, bn = blockIdx.x * 128;
    const int wm = (wid >> 2) * 64, wn = (wid & 3) * 32;

    // ldmatrix per-thread invariants (row&7 == lane&7 for both operands)
    const uint32_t xm   = (uint32_t)(lane & 7);
    const uint32_t rowA = (uint32_t)(wm + (lane & 15)) * 128;
    const uint32_t rowB = (uint32_t)(wn + (lane & 7) + ((lane >> 4) & 1) * 8) * 128;
    const int cA0 = (lane >> 4);         // 0..1
    const int cB0 = ((lane >> 3) & 1);   // 0..1

    float acc[4][4][4];
    #pragma unroll
    for (int i = 0; i < 4; i++)
        #pragma unroll
        for (int j = 0; j < 4; j++)
            #pragma unroll
            for (int q = 0; q < 4; q++) acc[i][j][q] = 0.0f;

    // cp.async per-thread invariants: 256 threads cover 32 rows x 8 chunks
    const int cr = tid >> 3, cc = tid & 7;
    const __nv_bfloat16* Ag = A  + (size_t)(bm + cr) * ROWE + cc * 8;
    const __nv_bfloat16* Bg = Bm + (size_t)(bn + cr) * ROWE + cc * 8;
    const uint32_t soff = (uint32_t)(cr * 128 + ((cc ^ (cr & 7)) << 4));

    auto load_stage = [&](int kc, int buf) {
        const uint32_t sA = sbase + (uint32_t)buf * STAGE_BYTES;
        const uint32_t sB = sA + 16384;
        #pragma unroll
        for (int i = 0; i < 4; i++) {
            cp16(sA + soff + i * 32 * 128, Ag + (size_t)i * 32 * ROWE + kc * 64);
            cp16(sB + soff + i * 32 * 128, Bg + (size_t)i * 32 * ROWE + kc * 64);
        }
    };

    auto compute_stage = [&](int buf) {
        const uint32_t sA = sbase + (uint32_t)buf * STAGE_BYTES;
        const uint32_t sB = sA + 16384;
        #pragma unroll
        for (int s = 0; s < 2; s++) {
            const uint32_t ca = (uint32_t)(s * 2 + cA0);
            const uint32_t cb = (uint32_t)(s * 2 + cB0);
            uint32_t aH[4][4];
            #pragma unroll
            for (int mt = 0; mt < 4; mt++)
                ldsm4(aH[mt], sA + rowA + mt * 2048 + ((ca ^ xm) << 4));
            uint32_t bH[4][2];
            #pragma unroll
            for (int np = 0; np < 2; np++) {
                uint32_t t[4];
                ldsm4(t, sB + rowB + np * 2048 + ((cb ^ xm) << 4));
                bH[np * 2 + 0][0] = t[0]; bH[np * 2 + 0][1] = t[1];
                bH[np * 2 + 1][0] = t[2]; bH[np * 2 + 1][1] = t[3];
            }
            #pragma unroll
            for (int mt = 0; mt < 4; mt++)
                #pragma unroll
                for (int nt = 0; nt < 4; nt++)
                    mma16816(acc[mt][nt], aH[mt], bH[nt]);
            {   // aH * bL
                uint32_t bL[4][2];
                #pragma unroll
                for (int np = 0; np < 2; np++) {
                    uint32_t t[4];
                    ldsm4(t, sB + rowB + np * 2048 + (((cb + 4) ^ xm) << 4));
                    bL[np * 2 + 0][0] = t[0]; bL[np * 2 + 0][1] = t[1];
                    bL[np * 2 + 1][0] = t[2]; bL[np * 2 + 1][1] = t[3];
                }
                #pragma unroll
                for (int mt = 0; mt < 4; mt++)
                    #pragma unroll
                    for (int nt = 0; nt < 4; nt++)
                        mma16816(acc[mt][nt], aH[mt], bL[nt]);
            }
            {   // aL * bH
                uint32_t aL[4][4];
                #pragma unroll
                for (int mt = 0; mt < 4; mt++)
                    ldsm4(aL[mt], sA + rowA + mt * 2048 + (((ca + 4) ^ xm) << 4));
                #pragma unroll
                for (int mt = 0; mt < 4; mt++)
                    #pragma unroll
                    for (int nt = 0; nt < 4; nt++)
                        mma16816(acc[mt][nt], aL[mt], bH[nt]);
            }
        }
    };

    // 3-stage pipeline, FULLY UNROLLED so buf/addresses are compile-time.
    load_stage(0, 0);
    asm volatile("cp.async.commit_group;" ::: "memory");
    load_stage(1, 1);
    asm volatile("cp.async.commit_group;" ::: "memory");

    #pragma unroll
    for (int kc = 0; kc < 16; kc++) {
        asm volatile("cp.async.wait_group 1;" ::: "memory");
        __syncthreads();            // stage kc visible; stage (kc+2)%3 free
        if (kc + 2 < 16)
            load_stage(kc + 2, (kc + 2) % 3);
        asm volatile("cp.async.commit_group;" ::: "memory");
        compute_stage(kc % 3);
    }

    // Epilogue
    const int gp = lane >> 2, tg = lane & 3;
    #pragma unroll
    for (int mt = 0; mt < 4; mt++) {
        const int m0 = bm + wm + mt * 16 + gp;
        #pragma unroll
        for (int nt = 0; nt < 4; nt++) {
            const int n = bn + wn + nt * 8 + tg * 2;
            float d0 = acc[mt][nt][0], d1 = acc[mt][nt][1];
            float d2 = acc[mt][nt][2], d3 = acc[mt][nt][3];
            if (TANH) {
                const float b0 = __ldg(bias + n), b1 = __ldg(bias + n + 1);
                d0 = fast_tanh(d0 + b0); d1 = fast_tanh(d1 + b1);
                d2 = fast_tanh(d2 + b0); d3 = fast_tanh(d3 + b1);
                __nv_bfloat16 h0, l0, h1, l1;
                split_bf16(d0, h0, l0); split_bf16(d1, h1, l1);
                __nv_bfloat16* p = Chl + (size_t)m0 * ROWE + (n >> 5) * 64 + (n & 31);
                __nv_bfloat162 hp, lp;
                hp.x = h0; hp.y = h1; lp.x = l0; lp.y = l1;
                *reinterpret_cast<__nv_bfloat162*>(p)      = hp;
                *reinterpret_cast<__nv_bfloat162*>(p + 32) = lp;
                split_bf16(d2, h0, l0); split_bf16(d3, h1, l1);
                p += (size_t)8 * ROWE;
                hp.x = h0; hp.y = h1; lp.x = l0; lp.y = l1;
                *reinterpret_cast<__nv_bfloat162*>(p)      = hp;
                *reinterpret_cast<__nv_bfloat162*>(p + 32) = lp;
            } else {
                float2 v0; v0.x = d0; v0.y = d1;
                float2 v1; v1.x = d2; v1.y = d3;
                *reinterpret_cast<float2*>(Cf + (size_t)m0 * EDIM + n)       = v0;
                *reinterpret_cast<float2*>(Cf + (size_t)(m0 + 8) * EDIM + n) = v1;
            }
        }
    }
}

// ---------------------------------------------------------------------------
// Softmax pass 1: per (batch, L-chunk) online-softmax partials per feature.
// ---------------------------------------------------------------------------
__global__ __launch_bounds__(512) void softmax_part(
    const float* __restrict__ att, const float* __restrict__ enc,
    const int* __restrict__ lengths,
    float* __restrict__ pm, float* __restrict__ ps, float* __restrict__ pa)
{
    const int b = blockIdx.y, c = blockIdx.x, e = threadIdx.x;
    const int len = lengths[b];
    const int l0 = c * LCH;
    const int l1 = min(l0 + LCH, len);

    const float* ap = att + ((size_t)b * SEQL + l0) * EDIM + e;
    const float* ep = enc + ((size_t)b * SEQL + l0) * EDIM + e;

    float m = -INFINITY, s = 0.0f, acc = 0.0f;
    for (int l = l0; l < l1; l++) {
        float x = *ap; float v = *ep;
        ap += EDIM; ep += EDIM;
        float mn   = fmaxf(m, x);
        float corr = __expf(m - mn);
        float p    = __expf(x - mn);
        s   = s * corr + p;
        acc = acc * corr + p * v;
        m = mn;
    }
    const size_t o = ((size_t)b * NCH + c) * EDIM + e;
    pm[o] = m; ps[o] = s; pa[o] = acc;
}

__global__ __launch_bounds__(512) void softmax_merge(
    const float* __restrict__ pm, const float* __restrict__ ps,
    const float* __restrict__ pa, float* __restrict__ out)
{
    const int b = blockIdx.x, e = threadIdx.x;
    float M = -INFINITY;
    #pragma unroll 4
    for (int c = 0; c < NCH; c++)
        M = fmaxf(M, pm[((size_t)b * NCH + c) * EDIM + e]);
    float S = 0.0f, Acc = 0.0f;
    #pragma unroll 4
    for (int c = 0; c < NCH; c++) {
        const size_t o = ((size_t)b * NCH + c) * EDIM + e;
        const float w = __expf(pm[o] - M);
        S   += ps[o] * w;
        Acc += pa[o] * w;
    }
    out[(size_t)b * EDIM + e] = Acc / S;
}

// ---------------------------------------------------------------------------
// Inputs: encodings [B,L,E] f32, lengths [B] i32, W_h [E,H] f32,
//         b_h [H] f32, W_c [H,E] f32. Output: [B,1,E] f32.
// ---------------------------------------------------------------------------
extern "C" void kernel_launch(void* const* d_in, const int* in_sizes, int n_in,
                              void* d_out, int out_size)
{
    const float* enc = (const float*)d_in[0];
    const int*   len = (const int*)  d_in[1];
    const float* W_h = (const float*)d_in[2];
    const float* b_h = (const float*)d_in[3];
    const float* W_c = (const float*)d_in[4];
    float* out = (float*)d_out;

    __nv_bfloat16 *encHL, *hHL, *WhHL, *WcHL;
    float *att, *pm, *ps, *pa;
    cudaGetSymbolAddress((void**)&encHL, g_encHL);
    cudaGetSymbolAddress((void**)&hHL,   g_hHL);
    cudaGetSymbolAddress((void**)&WhHL,  g_WhHL);
    cudaGetSymbolAddress((void**)&WcHL,  g_WcHL);
    cudaGetSymbolAddress((void**)&att,   g_att);
    cudaGetSymbolAddress((void**)&pm,    g_pm);
    cudaGetSymbolAddress((void**)&ps,    g_ps);
    cudaGetSymbolAddress((void**)&pa,    g_pa);

    cudaFuncSetAttribute(gemm_bf16x3<true>,
        cudaFuncAttributeMaxDynamicSharedMemorySize, GEMM_SMEM);
    cudaFuncSetAttribute(gemm_bf16x3<false>,
        cudaFuncAttributeMaxDynamicSharedMemorySize, GEMM_SMEM);

    convert_A<<<(MTOT * 128) / 256, 256>>>(enc, encHL);
    convert_W<<<(512 * 512) / 256, 256>>>(W_h, WhHL);
    convert_W<<<(512 * 512) / 256, 256>>>(W_c, WcHL);

    dim3 gg(4, MTOT / 128);   // (N/128, M/128)
    gemm_bf16x3<true ><<<gg, 256, GEMM_SMEM>>>(encHL, WhHL, b_h, nullptr, hHL);
    gemm_bf16x3<false><<<gg, 256, GEMM_SMEM>>>(hHL,   WcHL, nullptr, att, nullptr);

    dim3 gs(NCH, BATCH);
    softmax_part<<<gs, EDIM>>>(att, enc, len, pm, ps, pa);
    softmax_merge<<<BATCH, EDIM>>>(pm, ps, pa, out);
}

// round 7
// speedup vs baseline: 3.5189x; 1.0597x over previous
#include <cuda_runtime.h>
#include <cuda_bf16.h>
#include <math.h>
#include <stdint.h>

// Problem constants
#define BATCH 32
#define SEQL  2048
#define EDIM  512
#define HDIM  512
#define KDIM  512
#define MTOT  (BATCH * SEQL)     // 65536
#define NCH2  16                 // softmax chunks = 2048/128 (one per GEMM2 CTA row-tile)
#define ROWE  1024               // bf16 elems per row in HL layout: (512/32)*64

// HL layout: row r, k: offset = r*1024 + (k/32)*64 + part*32 + (k%32)
__device__ __nv_bfloat16 g_encHL[(size_t)MTOT * ROWE];
__device__ __nv_bfloat16 g_hHL  [(size_t)MTOT * ROWE];
__device__ __nv_bfloat16 g_WhHL [(size_t)HDIM * ROWE];   // B operand: [n][k...]
__device__ __nv_bfloat16 g_WcHL [(size_t)EDIM * ROWE];
__device__ float g_pm [BATCH * NCH2 * EDIM];
__device__ float g_ps [BATCH * NCH2 * EDIM];
__device__ float g_pa [BATCH * NCH2 * EDIM];

// ---------------------------------------------------------------------------
// helpers
// ---------------------------------------------------------------------------
__device__ __forceinline__ uint32_t s2u(const void* p) {
    uint32_t a;
    asm("{ .reg .u64 t; cvta.to.shared.u64 t, %1; cvt.u32.u64 %0, t; }"
        : "=r"(a) : "l"(p));
    return a;
}
__device__ __forceinline__ void cp16(uint32_t dst, const void* src) {
    asm volatile("cp.async.cg.shared.global [%0], [%1], 16;"
                 :: "r"(dst), "l"(src) : "memory");
}
__device__ __forceinline__ void ldsm4(uint32_t* r, uint32_t addr) {
    asm volatile("ldmatrix.sync.aligned.m8n8.x4.shared.b16 {%0,%1,%2,%3}, [%4];"
                 : "=r"(r[0]), "=r"(r[1]), "=r"(r[2]), "=r"(r[3]) : "r"(addr));
}
__device__ __forceinline__ void mma16816(float* d, const uint32_t* a,
                                         const uint32_t* b) {
    asm volatile(
        "mma.sync.aligned.m16n8k16.row.col.f32.bf16.bf16.f32 "
        "{%0,%1,%2,%3},{%4,%5,%6,%7},{%8,%9},{%0,%1,%2,%3};"
        : "+f"(d[0]), "+f"(d[1]), "+f"(d[2]), "+f"(d[3])
        : "r"(a[0]), "r"(a[1]), "r"(a[2]), "r"(a[3]), "r"(b[0]), "r"(b[1]));
}
__device__ __forceinline__ void split_bf16(float v, __nv_bfloat16& h,
                                           __nv_bfloat16& l) {
    h = __float2bfloat16(v);
    l = __float2bfloat16(v - __bfloat162float(h));
}
// fast tanh: (e^{2x}-1)/(e^{2x}+1), clamp avoids inf/inf; err ~1e-6.
__device__ __forceinline__ float fast_tanh(float x) {
    x = fminf(fmaxf(x, -15.0f), 15.0f);
    const float e = __expf(2.0f * x);
    return __fdividef(e - 1.0f, e + 1.0f);
}

// ---------------------------------------------------------------------------
// convert encodings fp32 [M][512] -> HL layout.
// ---------------------------------------------------------------------------
__global__ __launch_bounds__(256) void convert_A(
    const float* __restrict__ src, __nv_bfloat16* __restrict__ dst)
{
    const size_t g = (size_t)blockIdx.x * 256 + threadIdx.x;   // M*128 threads
    const int m  = (int)(g >> 7);
    const int kq = (int)(g & 127);
    const int k  = kq * 4;
    float4 v = *reinterpret_cast<const float4*>(src + (size_t)m * KDIM + k);
    __nv_bfloat16 h[4], l[4];
    split_bf16(v.x, h[0], l[0]);
    split_bf16(v.y, h[1], l[1]);
    split_bf16(v.z, h[2], l[2]);
    split_bf16(v.w, h[3], l[3]);
    __nv_bfloat16* p = dst + (size_t)m * ROWE + (k >> 5) * 64 + (k & 31);
    *reinterpret_cast<uint2*>(p)      = *reinterpret_cast<uint2*>(h);
    *reinterpret_cast<uint2*>(p + 32) = *reinterpret_cast<uint2*>(l);
}

// ---------------------------------------------------------------------------
// convert W fp32 [K][N] -> N-major HL layout [n][k...].
// ---------------------------------------------------------------------------
__global__ __launch_bounds__(256) void convert_W(
    const float* __restrict__ W, __nv_bfloat16* __restrict__ dst)
{
    const int g = blockIdx.x * 256 + threadIdx.x;   // 512*512 threads
    const int k = g >> 9;
    const int n = g & 511;
    __nv_bfloat16 h, l;
    split_bf16(W[(size_t)k * 512 + n], h, l);
    __nv_bfloat16* p = dst + (size_t)n * ROWE + (k >> 5) * 64 + (k & 31);
    p[0]  = h;
    p[32] = l;
}

// ---------------------------------------------------------------------------
// bf16x3 tensor-core GEMM: CTA tile 128x128, 8 warps (2m x 4n), warp 64x32,
// k=32/stage, 3-stage cp.async pipeline, fully unrolled, 2 CTAs/SM.
// TANH=true : h = tanh(A@B + bias), written as HL bf16 (for GEMM2).
// TANH=false: att tile kept in registers; fused masked-softmax partial
//             reduction over the CTA's 128 rows (one batch chunk), weighted
//             by enc (loaded fp32 into freed pipeline smem). Writes only
//             [B][16][E] partials (m, s, a) — att never touches DRAM.
// ---------------------------------------------------------------------------
#define STAGE_BYTES 32768
#define GEMM_SMEM   (3 * STAGE_BYTES)

template <bool TANH>
__global__ void __launch_bounds__(256, 2) gemm_bf16x3(
    const __nv_bfloat16* __restrict__ A, const __nv_bfloat16* __restrict__ Bm,
    const float* __restrict__ bias, __nv_bfloat16* __restrict__ Chl,
    const float* __restrict__ Enc, const int* __restrict__ lengths,
    float* __restrict__ pm, float* __restrict__ ps, float* __restrict__ pa)
{
    extern __shared__ char smem[];
    const uint32_t sbase = s2u(smem);
    const int tid  = threadIdx.x;
    const int wid  = tid >> 5, lane = tid & 31;
    const int bm = blockIdx.y * 128, bn = blockIdx.x * 128;
    const int wm = (wid >> 2) * 64, wn = (wid & 3) * 32;

    // ldmatrix per-thread invariants (row&7 == lane&7 for both operands)
    const uint32_t xm   = (uint32_t)(lane & 7);
    const uint32_t rowA = (uint32_t)(wm + (lane & 15)) * 128;
    const uint32_t rowB = (uint32_t)(wn + (lane & 7) + ((lane >> 4) & 1) * 8) * 128;
    const int cA0 = (lane >> 4);         // 0..1
    const int cB0 = ((lane >> 3) & 1);   // 0..1

    float acc[4][4][4];
    #pragma unroll
    for (int i = 0; i < 4; i++)
        #pragma unroll
        for (int j = 0; j < 4; j++)
            #pragma unroll
            for (int q = 0; q < 4; q++) acc[i][j][q] = 0.0f;

    // cp.async per-thread invariants: 256 threads cover 32 rows x 8 chunks
    const int cr = tid >> 3, cc = tid & 7;
    const __nv_bfloat16* Ag = A  + (size_t)(bm + cr) * ROWE + cc * 8;
    const __nv_bfloat16* Bg = Bm + (size_t)(bn + cr) * ROWE + cc * 8;
    const uint32_t soff = (uint32_t)(cr * 128 + ((cc ^ (cr & 7)) << 4));

    auto load_stage = [&](int kc, int buf) {
        const uint32_t sA = sbase + (uint32_t)buf * STAGE_BYTES;
        const uint32_t sB = sA + 16384;
        #pragma unroll
        for (int i = 0; i < 4; i++) {
            cp16(sA + soff + i * 32 * 128, Ag + (size_t)i * 32 * ROWE + kc * 64);
            cp16(sB + soff + i * 32 * 128, Bg + (size_t)i * 32 * ROWE + kc * 64);
        }
    };

    auto compute_stage = [&](int buf) {
        const uint32_t sA = sbase + (uint32_t)buf * STAGE_BYTES;
        const uint32_t sB = sA + 16384;
        #pragma unroll
        for (int s = 0; s < 2; s++) {
            const uint32_t ca = (uint32_t)(s * 2 + cA0);
            const uint32_t cb = (uint32_t)(s * 2 + cB0);
            uint32_t aH[4][4];
            #pragma unroll
            for (int mt = 0; mt < 4; mt++)
                ldsm4(aH[mt], sA + rowA + mt * 2048 + ((ca ^ xm) << 4));
            uint32_t bH[4][2];
            #pragma unroll
            for (int np = 0; np < 2; np++) {
                uint32_t t[4];
                ldsm4(t, sB + rowB + np * 2048 + ((cb ^ xm) << 4));
                bH[np * 2 + 0][0] = t[0]; bH[np * 2 + 0][1] = t[1];
                bH[np * 2 + 1][0] = t[2]; bH[np * 2 + 1][1] = t[3];
            }
            #pragma unroll
            for (int mt = 0; mt < 4; mt++)
                #pragma unroll
                for (int nt = 0; nt < 4; nt++)
                    mma16816(acc[mt][nt], aH[mt], bH[nt]);
            {   // aH * bL
                uint32_t bL[4][2];
                #pragma unroll
                for (int np = 0; np < 2; np++) {
                    uint32_t t[4];
                    ldsm4(t, sB + rowB + np * 2048 + (((cb + 4) ^ xm) << 4));
                    bL[np * 2 + 0][0] = t[0]; bL[np * 2 + 0][1] = t[1];
                    bL[np * 2 + 1][0] = t[2]; bL[np * 2 + 1][1] = t[3];
                }
                #pragma unroll
                for (int mt = 0; mt < 4; mt++)
                    #pragma unroll
                    for (int nt = 0; nt < 4; nt++)
                        mma16816(acc[mt][nt], aH[mt], bL[nt]);
            }
            {   // aL * bH
                uint32_t aL[4][4];
                #pragma unroll
                for (int mt = 0; mt < 4; mt++)
                    ldsm4(aL[mt], sA + rowA + mt * 2048 + (((ca + 4) ^ xm) << 4));
                #pragma unroll
                for (int mt = 0; mt < 4; mt++)
                    #pragma unroll
                    for (int nt = 0; nt < 4; nt++)
                        mma16816(acc[mt][nt], aL[mt], bH[nt]);
            }
        }
    };

    // 3-stage pipeline, fully unrolled so buf/addresses are compile-time.
    load_stage(0, 0);
    asm volatile("cp.async.commit_group;" ::: "memory");
    load_stage(1, 1);
    asm volatile("cp.async.commit_group;" ::: "memory");

    #pragma unroll
    for (int kc = 0; kc < 16; kc++) {
        asm volatile("cp.async.wait_group 1;" ::: "memory");
        __syncthreads();            // stage kc visible; stage (kc+2)%3 free
        if (kc + 2 < 16)
            load_stage(kc + 2, (kc + 2) % 3);
        asm volatile("cp.async.commit_group;" ::: "memory");
        compute_stage(kc % 3);
    }

    const int gp = lane >> 2, tg = lane & 3;

    if (TANH) {
        // --- GEMM1 epilogue: bias + tanh, write h in HL layout ---
        #pragma unroll
        for (int mt = 0; mt < 4; mt++) {
            const int m0 = bm + wm + mt * 16 + gp;
            #pragma unroll
            for (int nt = 0; nt < 4; nt++) {
                const int n = bn + wn + nt * 8 + tg * 2;
                float d0 = acc[mt][nt][0], d1 = acc[mt][nt][1];
                float d2 = acc[mt][nt][2], d3 = acc[mt][nt][3];
                const float b0 = __ldg(bias + n), b1 = __ldg(bias + n + 1);
                d0 = fast_tanh(d0 + b0); d1 = fast_tanh(d1 + b1);
                d2 = fast_tanh(d2 + b0); d3 = fast_tanh(d3 + b1);
                __nv_bfloat16 h0, l0, h1, l1;
                split_bf16(d0, h0, l0); split_bf16(d1, h1, l1);
                __nv_bfloat16* p = Chl + (size_t)m0 * ROWE + (n >> 5) * 64 + (n & 31);
                __nv_bfloat162 hp, lp;
                hp.x = h0; hp.y = h1; lp.x = l0; lp.y = l1;
                *reinterpret_cast<__nv_bfloat162*>(p)      = hp;
                *reinterpret_cast<__nv_bfloat162*>(p + 32) = lp;
                split_bf16(d2, h0, l0); split_bf16(d3, h1, l1);
                p += (size_t)8 * ROWE;
                hp.x = h0; hp.y = h1; lp.x = l0; lp.y = l1;
                *reinterpret_cast<__nv_bfloat162*>(p)      = hp;
                *reinterpret_cast<__nv_bfloat162*>(p + 32) = lp;
            }
        }
    } else {
        // --- GEMM2 fused epilogue: masked softmax partials over 128 rows ---
        const int batch = bm >> 11;          // 2048 rows per batch
        const int l0    = bm & 2047;
        const int chunk = l0 >> 7;           // 0..15
        const int len   = lengths[batch];

        // CRITICAL: all warps must finish reading pipeline stage 0/1 before
        // we overwrite them with the enc tile (race -> NaN in round 6).
        __syncthreads();

        // Load enc fp32 tile [128 rows x 128 cols] into stages 0-1 (64KB),
        // 16B-chunk XOR swizzle keyed by row&7 (conflict-free strided reads).
        const float* Eg = Enc + (size_t)bm * EDIM + bn;
        #pragma unroll
        for (int i = 0; i < 16; i++) {
            const int id  = tid + i * 256;
            const int row = id >> 5, ch = id & 31;
            const uint32_t off = (uint32_t)(row * 512 + ((ch ^ (row & 7)) << 4));
            cp16(sbase + off, Eg + (size_t)row * EDIM + ch * 4);
        }
        asm volatile("cp.async.commit_group;" ::: "memory");
        asm volatile("cp.async.wait_group 0;" ::: "memory");
        __syncthreads();

        // Phase A: per-column max over this CTA's 128 rows (sentinel -1e30)
        float M[8];
        #pragma unroll
        for (int ci = 0; ci < 8; ci++) M[ci] = -1e30f;
        #pragma unroll
        for (int mt = 0; mt < 4; mt++)
            #pragma unroll
            for (int rp = 0; rp < 2; rp++) {
                const int lr = wm + mt * 16 + gp + rp * 8;
                const bool valid = (l0 + lr) < len;
                #pragma unroll
                for (int nt = 0; nt < 4; nt++)
                    #pragma unroll
                    for (int j = 0; j < 2; j++) {
                        const float x = valid ? acc[mt][nt][rp * 2 + j] : -1e30f;
                        M[nt * 2 + j] = fmaxf(M[nt * 2 + j], x);
                    }
            }
        #pragma unroll
        for (int ci = 0; ci < 8; ci++) {
            M[ci] = fmaxf(M[ci], __shfl_xor_sync(0xFFFFFFFFu, M[ci], 4));
            M[ci] = fmaxf(M[ci], __shfl_xor_sync(0xFFFFFFFFu, M[ci], 8));
            M[ci] = fmaxf(M[ci], __shfl_xor_sync(0xFFFFFFFFu, M[ci], 16));
        }
        float* smax = reinterpret_cast<float*>(smem + 65536);  // [8][32]
        if (gp == 0) {
            #pragma unroll
            for (int ci = 0; ci < 8; ci++) {
                const int col = (ci >> 1) * 8 + tg * 2 + (ci & 1);
                smax[wid * 32 + col] = M[ci];
            }
        }
        __syncthreads();
        #pragma unroll
        for (int ci = 0; ci < 8; ci++) {
            const int col = (ci >> 1) * 8 + tg * 2 + (ci & 1);
            M[ci] = fmaxf(M[ci], smax[(wid ^ 4) * 32 + col]);
        }

        // Phase B: Σ exp(x-M) and Σ exp(x-M)·enc  (1 exp per element)
        float S[8], Aa[8];
        #pragma unroll
        for (int ci = 0; ci < 8; ci++) { S[ci] = 0.0f; Aa[ci] = 0.0f; }
        #pragma unroll
        for (int mt = 0; mt < 4; mt++)
            #pragma unroll
            for (int rp = 0; rp < 2; rp++) {
                const int lr = wm + mt * 16 + gp + rp * 8;
                const bool valid = (l0 + lr) < len;
                #pragma unroll
                for (int nt = 0; nt < 4; nt++) {
                    const int n0 = wn + nt * 8 + tg * 2;
                    const uint32_t eoff = (uint32_t)(lr * 512 +
                        (((n0 >> 2) ^ (lr & 7)) << 4) + (n0 & 3) * 4);
                    const float2 ev =
                        *reinterpret_cast<const float2*>(smem + eoff);
                    #pragma unroll
                    for (int j = 0; j < 2; j++) {
                        const float x = valid ? acc[mt][nt][rp * 2 + j] : -1e30f;
                        const float p = __expf(x - M[nt * 2 + j]);
                        S [nt * 2 + j] += p;
                        Aa[nt * 2 + j] += p * (j ? ev.y : ev.x);
                    }
                }
            }
        #pragma unroll
        for (int ci = 0; ci < 8; ci++) {
            #pragma unroll
            for (int msk = 4; msk <= 16; msk <<= 1) {
                S [ci] += __shfl_xor_sync(0xFFFFFFFFu, S [ci], msk);
                Aa[ci] += __shfl_xor_sync(0xFFFFFFFFu, Aa[ci], msk);
            }
        }
        float* ssum = smax + 256;   // [4 warps][32 cols][2]
        if (wid < 4 && gp == 0) {
            #pragma unroll
            for (int ci = 0; ci < 8; ci++) {
                const int col = (ci >> 1) * 8 + tg * 2 + (ci & 1);
                ssum[(wid * 32 + col) * 2 + 0] = S[ci];
                ssum[(wid * 32 + col) * 2 + 1] = Aa[ci];
            }
        }
        __syncthreads();
        if (wid >= 4 && gp == 0) {
            const size_t base = ((size_t)batch * NCH2 + chunk) * EDIM + bn + wn;
            #pragma unroll
            for (int ci = 0; ci < 8; ci++) {
                const int col = (ci >> 1) * 8 + tg * 2 + (ci & 1);
                pm[base + col] = M[ci];
                ps[base + col] = S[ci]  + ssum[((wid - 4) * 32 + col) * 2 + 0];
                pa[base + col] = Aa[ci] + ssum[((wid - 4) * 32 + col) * 2 + 1];
            }
        }
    }
}

// ---------------------------------------------------------------------------
// Merge NCH2 partials -> out[b][e].
// ---------------------------------------------------------------------------
__global__ __launch_bounds__(512) void softmax_merge(
    const float* __restrict__ pm, const float* __restrict__ ps,
    const float* __restrict__ pa, float* __restrict__ out)
{
    const int b = blockIdx.x, e = threadIdx.x;
    float M = -1e30f;
    #pragma unroll 4
    for (int c = 0; c < NCH2; c++)
        M = fmaxf(M, pm[((size_t)b * NCH2 + c) * EDIM + e]);
    float S = 0.0f, Acc = 0.0f;
    #pragma unroll 4
    for (int c = 0; c < NCH2; c++) {
        const size_t o = ((size_t)b * NCH2 + c) * EDIM + e;
        const float w = __expf(pm[o] - M);
        S   += ps[o] * w;
        Acc += pa[o] * w;
    }
    out[(size_t)b * EDIM + e] = Acc / S;
}

// ---------------------------------------------------------------------------
// Inputs: encodings [B,L,E] f32, lengths [B] i32, W_h [E,H] f32,
//         b_h [H] f32, W_c [H,E] f32. Output: [B,1,E] f32.
// ---------------------------------------------------------------------------
extern "C" void kernel_launch(void* const* d_in, const int* in_sizes, int n_in,
                              void* d_out, int out_size)
{
    const float* enc = (const float*)d_in[0];
    const int*   len = (const int*)  d_in[1];
    const float* W_h = (const float*)d_in[2];
    const float* b_h = (const float*)d_in[3];
    const float* W_c = (const float*)d_in[4];
    float* out = (float*)d_out;

    __nv_bfloat16 *encHL, *hHL, *WhHL, *WcHL;
    float *pm, *ps, *pa;
    cudaGetSymbolAddress((void**)&encHL, g_encHL);
    cudaGetSymbolAddress((void**)&hHL,   g_hHL);
    cudaGetSymbolAddress((void**)&WhHL,  g_WhHL);
    cudaGetSymbolAddress((void**)&WcHL,  g_WcHL);
    cudaGetSymbolAddress((void**)&pm,    g_pm);
    cudaGetSymbolAddress((void**)&ps,    g_ps);
    cudaGetSymbolAddress((void**)&pa,    g_pa);

    cudaFuncSetAttribute(gemm_bf16x3<true>,
        cudaFuncAttributeMaxDynamicSharedMemorySize, GEMM_SMEM);
    cudaFuncSetAttribute(gemm_bf16x3<false>,
        cudaFuncAttributeMaxDynamicSharedMemorySize, GEMM_SMEM);

    convert_A<<<(MTOT * 128) / 256, 256>>>(enc, encHL);
    convert_W<<<(512 * 512) / 256, 256>>>(W_h, WhHL);
    convert_W<<<(512 * 512) / 256, 256>>>(W_c, WcHL);

    dim3 gg(4, MTOT / 128);   // (N/128, M/128)
    gemm_bf16x3<true ><<<gg, 256, GEMM_SMEM>>>(
        encHL, WhHL, b_h, hHL, nullptr, nullptr, nullptr, nullptr, nullptr);
    gemm_bf16x3<false><<<gg, 256, GEMM_SMEM>>>(
        hHL, WcHL, nullptr, nullptr, enc, len, pm, ps, pa);

    softmax_merge<<<BATCH, EDIM>>>(pm, ps, pa, out);
}

// round 8
// speedup vs baseline: 3.5956x; 1.0218x over previous
#include <cuda_runtime.h>
#include <cuda_bf16.h>
#include <math.h>
#include <stdint.h>

// Problem constants
#define BATCH 32
#define SEQL  2048
#define EDIM  512
#define HDIM  512
#define KDIM  512
#define MTOT  (BATCH * SEQL)     // 65536
#define NCH2  16                 // softmax chunks = 2048/128 (one per GEMM2 CTA row-tile)
#define ROWE  1024               // bf16 elems per row in HL layout: (512/32)*64

// HL layout: row r, k: offset = r*1024 + (k/32)*64 + part*32 + (k%32)
__device__ __nv_bfloat16 g_encHL[(size_t)MTOT * ROWE];
__device__ __nv_bfloat16 g_hHL  [(size_t)MTOT * ROWE];
__device__ __nv_bfloat16 g_WhHL [(size_t)HDIM * ROWE];   // B operand: [n][k...]
__device__ __nv_bfloat16 g_WcHL [(size_t)EDIM * ROWE];
__device__ float g_pm [BATCH * NCH2 * EDIM];
__device__ float g_ps [BATCH * NCH2 * EDIM];
__device__ float g_pa [BATCH * NCH2 * EDIM];

// ---------------------------------------------------------------------------
// helpers
// ---------------------------------------------------------------------------
__device__ __forceinline__ uint32_t s2u(const void* p) {
    uint32_t a;
    asm("{ .reg .u64 t; cvta.to.shared.u64 t, %1; cvt.u32.u64 %0, t; }"
        : "=r"(a) : "l"(p));
    return a;
}
__device__ __forceinline__ void cp16(uint32_t dst, const void* src) {
    asm volatile("cp.async.cg.shared.global [%0], [%1], 16;"
                 :: "r"(dst), "l"(src) : "memory");
}
__device__ __forceinline__ void ldsm4(uint32_t* r, uint32_t addr) {
    asm volatile("ldmatrix.sync.aligned.m8n8.x4.shared.b16 {%0,%1,%2,%3}, [%4];"
                 : "=r"(r[0]), "=r"(r[1]), "=r"(r[2]), "=r"(r[3]) : "r"(addr));
}
__device__ __forceinline__ void mma16816(float* d, const uint32_t* a,
                                         const uint32_t* b) {
    asm volatile(
        "mma.sync.aligned.m16n8k16.row.col.f32.bf16.bf16.f32 "
        "{%0,%1,%2,%3},{%4,%5,%6,%7},{%8,%9},{%0,%1,%2,%3};"
        : "+f"(d[0]), "+f"(d[1]), "+f"(d[2]), "+f"(d[3])
        : "r"(a[0]), "r"(a[1]), "r"(a[2]), "r"(a[3]), "r"(b[0]), "r"(b[1]));
}
__device__ __forceinline__ void split_bf16(float v, __nv_bfloat16& h,
                                           __nv_bfloat16& l) {
    h = __float2bfloat16(v);
    l = __float2bfloat16(v - __bfloat162float(h));
}
// fast tanh: (e^{2x}-1)/(e^{2x}+1), clamp avoids inf/inf; err ~1e-6.
__device__ __forceinline__ float fast_tanh(float x) {
    x = fminf(fmaxf(x, -15.0f), 15.0f);
    const float e = __expf(2.0f * x);
    return __fdividef(e - 1.0f, e + 1.0f);
}

// ---------------------------------------------------------------------------
// convert encodings fp32 [M][512] -> HL layout. One thread = 8 k's of a row,
// producing one 16B hi store + one 16B lo store (full-sector coalescing).
// ---------------------------------------------------------------------------
__global__ __launch_bounds__(256) void convert_A(
    const float* __restrict__ src, __nv_bfloat16* __restrict__ dst)
{
    const size_t g = (size_t)blockIdx.x * 256 + threadIdx.x;   // M*64 threads
    const int m  = (int)(g >> 6);
    const int k  = (int)(g & 63) * 8;
    const float4 v0 = *reinterpret_cast<const float4*>(src + (size_t)m * KDIM + k);
    const float4 v1 = *reinterpret_cast<const float4*>(src + (size_t)m * KDIM + k + 4);
    __nv_bfloat16 h[8], l[8];
    split_bf16(v0.x, h[0], l[0]); split_bf16(v0.y, h[1], l[1]);
    split_bf16(v0.z, h[2], l[2]); split_bf16(v0.w, h[3], l[3]);
    split_bf16(v1.x, h[4], l[4]); split_bf16(v1.y, h[5], l[5]);
    split_bf16(v1.z, h[6], l[6]); split_bf16(v1.w, h[7], l[7]);
    __nv_bfloat16* p = dst + (size_t)m * ROWE + (k >> 5) * 64 + (k & 31);
    *reinterpret_cast<uint4*>(p)      = *reinterpret_cast<uint4*>(h);
    *reinterpret_cast<uint4*>(p + 32) = *reinterpret_cast<uint4*>(l);
}

// ---------------------------------------------------------------------------
// convert both W matrices fp32 [K][N] -> N-major HL layout [n][k...].
// blockIdx.y: 0 = W_h, 1 = W_c.
// ---------------------------------------------------------------------------
__global__ __launch_bounds__(256) void convert_W(
    const float* __restrict__ Wh, const float* __restrict__ Wc,
    __nv_bfloat16* __restrict__ dh, __nv_bfloat16* __restrict__ dc)
{
    const float* W = blockIdx.y ? Wc : Wh;
    __nv_bfloat16* dst = blockIdx.y ? dc : dh;
    const int g = blockIdx.x * 256 + threadIdx.x;   // 512*512 threads
    const int k = g >> 9;
    const int n = g & 511;
    __nv_bfloat16 h, l;
    split_bf16(W[(size_t)k * 512 + n], h, l);
    __nv_bfloat16* p = dst + (size_t)n * ROWE + (k >> 5) * 64 + (k & 31);
    p[0]  = h;
    p[32] = l;
}

// ---------------------------------------------------------------------------
// bf16x3 tensor-core GEMM: CTA tile 128x128, 8 warps (2m x 4n), warp 64x32,
// k=32/stage, 3-stage cp.async pipeline, fully unrolled, 2 CTAs/SM.
// TANH=true : h = tanh(A@B + bias) -> HL bf16, staged through smem for
//             fully-coalesced 16B global stores.
// TANH=false: fused masked-softmax partial reduction (att never hits DRAM).
// ---------------------------------------------------------------------------
#define STAGE_BYTES 32768
#define GEMM_SMEM   (3 * STAGE_BYTES)

template <bool TANH>
__global__ void __launch_bounds__(256, 2) gemm_bf16x3(
    const __nv_bfloat16* __restrict__ A, const __nv_bfloat16* __restrict__ Bm,
    const float* __restrict__ bias, __nv_bfloat16* __restrict__ Chl,
    const float* __restrict__ Enc, const int* __restrict__ lengths,
    float* __restrict__ pm, float* __restrict__ ps, float* __restrict__ pa)
{
    extern __shared__ char smem[];
    const uint32_t sbase = s2u(smem);
    const int tid  = threadIdx.x;
    const int wid  = tid >> 5, lane = tid & 31;
    const int bm = blockIdx.y * 128, bn = blockIdx.x * 128;
    const int wm = (wid >> 2) * 64, wn = (wid & 3) * 32;

    // ldmatrix per-thread invariants (row&7 == lane&7 for both operands)
    const uint32_t xm   = (uint32_t)(lane & 7);
    const uint32_t rowA = (uint32_t)(wm + (lane & 15)) * 128;
    const uint32_t rowB = (uint32_t)(wn + (lane & 7) + ((lane >> 4) & 1) * 8) * 128;
    const int cA0 = (lane >> 4);         // 0..1
    const int cB0 = ((lane >> 3) & 1);   // 0..1

    float acc[4][4][4];
    #pragma unroll
    for (int i = 0; i < 4; i++)
        #pragma unroll
        for (int j = 0; j < 4; j++)
            #pragma unroll
            for (int q = 0; q < 4; q++) acc[i][j][q] = 0.0f;

    // cp.async per-thread invariants: 256 threads cover 32 rows x 8 chunks
    const int cr = tid >> 3, cc = tid & 7;
    const __nv_bfloat16* Ag = A  + (size_t)(bm + cr) * ROWE + cc * 8;
    const __nv_bfloat16* Bg = Bm + (size_t)(bn + cr) * ROWE + cc * 8;
    const uint32_t soff = (uint32_t)(cr * 128 + ((cc ^ (cr & 7)) << 4));

    auto load_stage = [&](int kc, int buf) {
        const uint32_t sA = sbase + (uint32_t)buf * STAGE_BYTES;
        const uint32_t sB = sA + 16384;
        #pragma unroll
        for (int i = 0; i < 4; i++) {
            cp16(sA + soff + i * 32 * 128, Ag + (size_t)i * 32 * ROWE + kc * 64);
            cp16(sB + soff + i * 32 * 128, Bg + (size_t)i * 32 * ROWE + kc * 64);
        }
    };

    auto compute_stage = [&](int buf) {
        const uint32_t sA = sbase + (uint32_t)buf * STAGE_BYTES;
        const uint32_t sB = sA + 16384;
        #pragma unroll
        for (int s = 0; s < 2; s++) {
            const uint32_t ca = (uint32_t)(s * 2 + cA0);
            const uint32_t cb = (uint32_t)(s * 2 + cB0);
            uint32_t aH[4][4];
            #pragma unroll
            for (int mt = 0; mt < 4; mt++)
                ldsm4(aH[mt], sA + rowA + mt * 2048 + ((ca ^ xm) << 4));
            uint32_t bH[4][2];
            #pragma unroll
            for (int np = 0; np < 2; np++) {
                uint32_t t[4];
                ldsm4(t, sB + rowB + np * 2048 + ((cb ^ xm) << 4));
                bH[np * 2 + 0][0] = t[0]; bH[np * 2 + 0][1] = t[1];
                bH[np * 2 + 1][0] = t[2]; bH[np * 2 + 1][1] = t[3];
            }
            #pragma unroll
            for (int mt = 0; mt < 4; mt++)
                #pragma unroll
                for (int nt = 0; nt < 4; nt++)
                    mma16816(acc[mt][nt], aH[mt], bH[nt]);
            {   // aH * bL
                uint32_t bL[4][2];
                #pragma unroll
                for (int np = 0; np < 2; np++) {
                    uint32_t t[4];
                    ldsm4(t, sB + rowB + np * 2048 + (((cb + 4) ^ xm) << 4));
                    bL[np * 2 + 0][0] = t[0]; bL[np * 2 + 0][1] = t[1];
                    bL[np * 2 + 1][0] = t[2]; bL[np * 2 + 1][1] = t[3];
                }
                #pragma unroll
                for (int mt = 0; mt < 4; mt++)
                    #pragma unroll
                    for (int nt = 0; nt < 4; nt++)
                        mma16816(acc[mt][nt], aH[mt], bL[nt]);
            }
            {   // aL * bH
                uint32_t aL[4][4];
                #pragma unroll
                for (int mt = 0; mt < 4; mt++)
                    ldsm4(aL[mt], sA + rowA + mt * 2048 + (((ca + 4) ^ xm) << 4));
                #pragma unroll
                for (int mt = 0; mt < 4; mt++)
                    #pragma unroll
                    for (int nt = 0; nt < 4; nt++)
                        mma16816(acc[mt][nt], aL[mt], bH[nt]);
            }
        }
    };

    // 3-stage pipeline, fully unrolled so buf/addresses are compile-time.
    load_stage(0, 0);
    asm volatile("cp.async.commit_group;" ::: "memory");
    load_stage(1, 1);
    asm volatile("cp.async.commit_group;" ::: "memory");

    #pragma unroll
    for (int kc = 0; kc < 16; kc++) {
        asm volatile("cp.async.wait_group 1;" ::: "memory");
        __syncthreads();            // stage kc visible; stage (kc+2)%3 free
        if (kc + 2 < 16)
            load_stage(kc + 2, (kc + 2) % 3);
        asm volatile("cp.async.commit_group;" ::: "memory");
        compute_stage(kc % 3);
    }

    const int gp = lane >> 2, tg = lane & 3;

    if (TANH) {
        // --- GEMM1 epilogue: bias+tanh+split, staged via smem for coalesced
        //     16B global stores. smem tile: 128 rows x 512B (HL of 128 cols),
        //     16B-granule XOR swizzle keyed by row&7 (conflict-free). ---
        __syncthreads();   // drain pipeline-stage readers before smem reuse
        #pragma unroll
        for (int mt = 0; mt < 4; mt++) {
            #pragma unroll
            for (int nt = 0; nt < 4; nt++) {
                const int ln = wn + nt * 8 + tg * 2;       // local col
                const float b0 = __ldg(bias + bn + ln);
                const float b1 = __ldg(bias + bn + ln + 1);
                #pragma unroll
                for (int rp = 0; rp < 2; rp++) {
                    const int r = wm + mt * 16 + gp + rp * 8;   // local row
                    float d0 = fast_tanh(acc[mt][nt][rp * 2 + 0] + b0);
                    float d1 = fast_tanh(acc[mt][nt][rp * 2 + 1] + b1);
                    __nv_bfloat16 h0, l0, h1, l1;
                    split_bf16(d0, h0, l0); split_bf16(d1, h1, l1);
                    __nv_bfloat162 hp, lp;
                    hp.x = h0; hp.y = h1; lp.x = l0; lp.y = l1;
                    // within-row byte offset (unswizzled):
                    const uint32_t wh = (uint32_t)((ln >> 5) * 128 + (ln & 31) * 2);
                    const uint32_t wl = wh + 64;
                    const uint32_t swh = ((wh >> 4) ^ (uint32_t)(r & 7)) * 16 + (wh & 15);
                    const uint32_t swl = ((wl >> 4) ^ (uint32_t)(r & 7)) * 16 + (wl & 15);
                    *reinterpret_cast<__nv_bfloat162*>(smem + r * 512 + swh) = hp;
                    *reinterpret_cast<__nv_bfloat162*>(smem + r * 512 + swl) = lp;
                }
            }
        }
        __syncthreads();
        // Coalesced copy-out: 64KB = 4096 x 16B; row segment is 512B
        // contiguous in global HL layout.
        char* dstb = reinterpret_cast<char*>(Chl) + (size_t)bm * 2048 + (size_t)bn * 4;
        #pragma unroll
        for (int i = 0; i < 16; i++) {
            const int id  = tid + i * 256;        // 0..4095
            const int row = id >> 5;              // 32 x16B per row
            const uint32_t w  = (uint32_t)(id & 31) * 16;
            const uint32_t sw = ((w >> 4) ^ (uint32_t)(row & 7)) * 16;
            const uint4 v = *reinterpret_cast<uint4*>(smem + row * 512 + sw);
            *reinterpret_cast<uint4*>(dstb + (size_t)row * 2048 + w) = v;
        }
    } else {
        // --- GEMM2 fused epilogue: masked softmax partials over 128 rows ---
        const int batch = bm >> 11;          // 2048 rows per batch
        const int l0    = bm & 2047;
        const int chunk = l0 >> 7;           // 0..15
        const int len   = lengths[batch];

        // all warps must finish reading pipeline stages before smem reuse
        __syncthreads();

        // Load enc fp32 tile [128 rows x 128 cols] into stages 0-1 (64KB),
        // 16B-chunk XOR swizzle keyed by row&7 (conflict-free strided reads).
        const float* Eg = Enc + (size_t)bm * EDIM + bn;
        #pragma unroll
        for (int i = 0; i < 16; i++) {
            const int id  = tid + i * 256;
            const int row = id >> 5, ch = id & 31;
            const uint32_t off = (uint32_t)(row * 512 + ((ch ^ (row & 7)) << 4));
            cp16(sbase + off, Eg + (size_t)row * EDIM + ch * 4);
        }
        asm volatile("cp.async.commit_group;" ::: "memory");
        asm volatile("cp.async.wait_group 0;" ::: "memory");
        __syncthreads();

        // Phase A: per-column max over this CTA's 128 rows (sentinel -1e30)
        float M[8];
        #pragma unroll
        for (int ci = 0; ci < 8; ci++) M[ci] = -1e30f;
        #pragma unroll
        for (int mt = 0; mt < 4; mt++)
            #pragma unroll
            for (int rp = 0; rp < 2; rp++) {
                const int lr = wm + mt * 16 + gp + rp * 8;
                const bool valid = (l0 + lr) < len;
                #pragma unroll
                for (int nt = 0; nt < 4; nt++)
                    #pragma unroll
                    for (int j = 0; j < 2; j++) {
                        const float x = valid ? acc[mt][nt][rp * 2 + j] : -1e30f;
                        M[nt * 2 + j] = fmaxf(M[nt * 2 + j], x);
                    }
            }
        #pragma unroll
        for (int ci = 0; ci < 8; ci++) {
            M[ci] = fmaxf(M[ci], __shfl_xor_sync(0xFFFFFFFFu, M[ci], 4));
            M[ci] = fmaxf(M[ci], __shfl_xor_sync(0xFFFFFFFFu, M[ci], 8));
            M[ci] = fmaxf(M[ci], __shfl_xor_sync(0xFFFFFFFFu, M[ci], 16));
        }
        float* smax = reinterpret_cast<float*>(smem + 65536);  // [8][32]
        if (gp == 0) {
            #pragma unroll
            for (int ci = 0; ci < 8; ci++) {
                const int col = (ci >> 1) * 8 + tg * 2 + (ci & 1);
                smax[wid * 32 + col] = M[ci];
            }
        }
        __syncthreads();
        #pragma unroll
        for (int ci = 0; ci < 8; ci++) {
            const int col = (ci >> 1) * 8 + tg * 2 + (ci & 1);
            M[ci] = fmaxf(M[ci], smax[(wid ^ 4) * 32 + col]);
        }

        // Phase B: Σ exp(x-M) and Σ exp(x-M)·enc  (1 exp per element)
        float S[8], Aa[8];
        #pragma unroll
        for (int ci = 0; ci < 8; ci++) { S[ci] = 0.0f; Aa[ci] = 0.0f; }
        #pragma unroll
        for (int mt = 0; mt < 4; mt++)
            #pragma unroll
            for (int rp = 0; rp < 2; rp++) {
                const int lr = wm + mt * 16 + gp + rp * 8;
                const bool valid = (l0 + lr) < len;
                #pragma unroll
                for (int nt = 0; nt < 4; nt++) {
                    const int n0 = wn + nt * 8 + tg * 2;
                    const uint32_t eoff = (uint32_t)(lr * 512 +
                        (((n0 >> 2) ^ (lr & 7)) << 4) + (n0 & 3) * 4);
                    const float2 ev =
                        *reinterpret_cast<const float2*>(smem + eoff);
                    #pragma unroll
                    for (int j = 0; j < 2; j++) {
                        const float x = valid ? acc[mt][nt][rp * 2 + j] : -1e30f;
                        const float p = __expf(x - M[nt * 2 + j]);
                        S [nt * 2 + j] += p;
                        Aa[nt * 2 + j] += p * (j ? ev.y : ev.x);
                    }
                }
            }
        #pragma unroll
        for (int ci = 0; ci < 8; ci++) {
            #pragma unroll
            for (int msk = 4; msk <= 16; msk <<= 1) {
                S [ci] += __shfl_xor_sync(0xFFFFFFFFu, S [ci], msk);
                Aa[ci] += __shfl_xor_sync(0xFFFFFFFFu, Aa[ci], msk);
            }
        }
        float* ssum = smax + 256;   // [4 warps][32 cols][2]
        if (wid < 4 && gp == 0) {
            #pragma unroll
            for (int ci = 0; ci < 8; ci++) {
                const int col = (ci >> 1) * 8 + tg * 2 + (ci & 1);
                ssum[(wid * 32 + col) * 2 + 0] = S[ci];
                ssum[(wid * 32 + col) * 2 + 1] = Aa[ci];
            }
        }
        __syncthreads();
        if (wid >= 4 && gp == 0) {
            const size_t base = ((size_t)batch * NCH2 + chunk) * EDIM + bn + wn;
            #pragma unroll
            for (int ci = 0; ci < 8; ci++) {
                const int col = (ci >> 1) * 8 + tg * 2 + (ci & 1);
                pm[base + col] = M[ci];
                ps[base + col] = S[ci]  + ssum[((wid - 4) * 32 + col) * 2 + 0];
                pa[base + col] = Aa[ci] + ssum[((wid - 4) * 32 + col) * 2 + 1];
            }
        }
    }
}

// ---------------------------------------------------------------------------
// Merge NCH2 partials -> out[b][e].
// ---------------------------------------------------------------------------
__global__ __launch_bounds__(512) void softmax_merge(
    const float* __restrict__ pm, const float* __restrict__ ps,
    const float* __restrict__ pa, float* __restrict__ out)
{
    const int b = blockIdx.x, e = threadIdx.x;
    float M = -1e30f;
    #pragma unroll 4
    for (int c = 0; c < NCH2; c++)
        M = fmaxf(M, pm[((size_t)b * NCH2 + c) * EDIM + e]);
    float S = 0.0f, Acc = 0.0f;
    #pragma unroll 4
    for (int c = 0; c < NCH2; c++) {
        const size_t o = ((size_t)b * NCH2 + c) * EDIM + e;
        const float w = __expf(pm[o] - M);
        S   += ps[o] * w;
        Acc += pa[o] * w;
    }
    out[(size_t)b * EDIM + e] = Acc / S;
}

// ---------------------------------------------------------------------------
// Inputs: encodings [B,L,E] f32, lengths [B] i32, W_h [E,H] f32,
//         b_h [H] f32, W_c [H,E] f32. Output: [B,1,E] f32.
// ---------------------------------------------------------------------------
extern "C" void kernel_launch(void* const* d_in, const int* in_sizes, int n_in,
                              void* d_out, int out_size)
{
    const float* enc = (const float*)d_in[0];
    const int*   len = (const int*)  d_in[1];
    const float* W_h = (const float*)d_in[2];
    const float* b_h = (const float*)d_in[3];
    const float* W_c = (const float*)d_in[4];
    float* out = (float*)d_out;

    __nv_bfloat16 *encHL, *hHL, *WhHL, *WcHL;
    float *pm, *ps, *pa;
    cudaGetSymbolAddress((void**)&encHL, g_encHL);
    cudaGetSymbolAddress((void**)&hHL,   g_hHL);
    cudaGetSymbolAddress((void**)&WhHL,  g_WhHL);
    cudaGetSymbolAddress((void**)&WcHL,  g_WcHL);
    cudaGetSymbolAddress((void**)&pm,    g_pm);
    cudaGetSymbolAddress((void**)&ps,    g_ps);
    cudaGetSymbolAddress((void**)&pa,    g_pa);

    cudaFuncSetAttribute(gemm_bf16x3<true>,
        cudaFuncAttributeMaxDynamicSharedMemorySize, GEMM_SMEM);
    cudaFuncSetAttribute(gemm_bf16x3<false>,
        cudaFuncAttributeMaxDynamicSharedMemorySize, GEMM_SMEM);

    convert_A<<<(MTOT * 64) / 256, 256>>>(enc, encHL);
    dim3 gw((512 * 512) / 256, 2);
    convert_W<<<gw, 256>>>(W_h, W_c, WhHL, WcHL);

    dim3 gg(4, MTOT / 128);   // (N/128, M/128)
    gemm_bf16x3<true ><<<gg, 256, GEMM_SMEM>>>(
        encHL, WhHL, b_h, hHL, nullptr, nullptr, nullptr, nullptr, nullptr);
    gemm_bf16x3<false><<<gg, 256, GEMM_SMEM>>>(
        hHL, WcHL, nullptr, nullptr, enc, len, pm, ps, pa);

    softmax_merge<<<BATCH, EDIM>>>(pm, ps, pa, out);
}

// round 9
// speedup vs baseline: 4.9745x; 1.3835x over previous
#include <cuda_runtime.h>
#include <cuda_fp16.h>
#include <math.h>
#include <stdint.h>

// Problem constants
#define BATCH 32
#define SEQL  2048
#define EDIM  512
#define HDIM  512
#define KDIM  512
#define MTOT  (BATCH * SEQL)     // 65536
#define NCH2  16                 // softmax chunks = 2048/128
#define ROWB  1024               // fp16 elems per B n-row: (512/32)*64 (HL pairs)

// A operands: plain fp16 row-major [M][512]. B operands: HL fp16 [n][k...].
__device__ __half g_encF[(size_t)MTOT * 512];
__device__ __half g_hF  [(size_t)MTOT * 512];
__device__ __half g_WhHL[(size_t)HDIM * ROWB];
__device__ __half g_WcHL[(size_t)EDIM * ROWB];
__device__ float g_pm [BATCH * NCH2 * EDIM];
__device__ float g_ps [BATCH * NCH2 * EDIM];
__device__ float g_pa [BATCH * NCH2 * EDIM];

// ---------------------------------------------------------------------------
// helpers
// ---------------------------------------------------------------------------
__device__ __forceinline__ uint32_t s2u(const void* p) {
    uint32_t a;
    asm("{ .reg .u64 t; cvta.to.shared.u64 t, %1; cvt.u32.u64 %0, t; }"
        : "=r"(a) : "l"(p));
    return a;
}
__device__ __forceinline__ void cp16(uint32_t dst, const void* src) {
    asm volatile("cp.async.cg.shared.global [%0], [%1], 16;"
                 :: "r"(dst), "l"(src) : "memory");
}
__device__ __forceinline__ void ldsm4(uint32_t* r, uint32_t addr) {
    asm volatile("ldmatrix.sync.aligned.m8n8.x4.shared.b16 {%0,%1,%2,%3}, [%4];"
                 : "=r"(r[0]), "=r"(r[1]), "=r"(r[2]), "=r"(r[3]) : "r"(addr));
}
__device__ __forceinline__ void mma16816h(float* d, const uint32_t* a,
                                          const uint32_t* b) {
    asm volatile(
        "mma.sync.aligned.m16n8k16.row.col.f32.f16.f16.f32 "
        "{%0,%1,%2,%3},{%4,%5,%6,%7},{%8,%9},{%0,%1,%2,%3};"
        : "+f"(d[0]), "+f"(d[1]), "+f"(d[2]), "+f"(d[3])
        : "r"(a[0]), "r"(a[1]), "r"(a[2]), "r"(a[3]), "r"(b[0]), "r"(b[1]));
}
// fast tanh: (e^{2x}-1)/(e^{2x}+1), clamp avoids inf/inf; err ~1e-6.
__device__ __forceinline__ float fast_tanh(float x) {
    x = fminf(fmaxf(x, -15.0f), 15.0f);
    const float e = __expf(2.0f * x);
    return __fdividef(e - 1.0f, e + 1.0f);
}

// ---------------------------------------------------------------------------
// convert encodings fp32 [M][512] -> plain fp16. 8 elems/thread, 16B store.
// ---------------------------------------------------------------------------
__global__ __launch_bounds__(256) void convert_A(
    const float* __restrict__ src, __half* __restrict__ dst)
{
    const size_t g = (size_t)blockIdx.x * 256 + threadIdx.x;   // M*64 threads
    const int m = (int)(g >> 6);
    const int k = (int)(g & 63) * 8;
    const float4 v0 = *reinterpret_cast<const float4*>(src + (size_t)m * KDIM + k);
    const float4 v1 = *reinterpret_cast<const float4*>(src + (size_t)m * KDIM + k + 4);
    __half2 h[4];
    h[0] = __floats2half2_rn(v0.x, v0.y);
    h[1] = __floats2half2_rn(v0.z, v0.w);
    h[2] = __floats2half2_rn(v1.x, v1.y);
    h[3] = __floats2half2_rn(v1.z, v1.w);
    *reinterpret_cast<uint4*>(dst + (size_t)m * 512 + k) =
        *reinterpret_cast<uint4*>(h);
}

// ---------------------------------------------------------------------------
// convert both W matrices fp32 [K][N] -> N-major HL fp16 [n][k...].
// ---------------------------------------------------------------------------
__global__ __launch_bounds__(256) void convert_W(
    const float* __restrict__ Wh, const float* __restrict__ Wc,
    __half* __restrict__ dh, __half* __restrict__ dc)
{
    const float* W = blockIdx.y ? Wc : Wh;
    __half* dst = blockIdx.y ? dc : dh;
    const int g = blockIdx.x * 256 + threadIdx.x;   // 512*512 threads
    const int k = g >> 9;
    const int n = g & 511;
    const float w = W[(size_t)k * 512 + n];
    const __half h = __float2half_rn(w);
    const __half l = __float2half_rn(w - __half2float(h));
    __half* p = dst + (size_t)n * ROWB + (k >> 5) * 64 + (k & 31);
    p[0]  = h;
    p[32] = l;
}

// ---------------------------------------------------------------------------
// fp16x2 tensor-core GEMM: C = fp16(A)[M,512] @ (bH+bL). 2 MMA passes.
// CTA tile 128x128, 8 warps (2m x 4n), warp 64x32, k=32/stage,
// 4-stage cp.async pipeline, fully unrolled, 2 CTAs/SM.
// Stage: A plain fp16 128x32 = 8KB @+0; B HL 128x(32x2) = 16KB @+8192.
// TANH=true : h = tanh(A@B + bias) -> plain fp16, smem-staged stores.
// TANH=false: fused masked-softmax partial reduction (att never hits DRAM).
// ---------------------------------------------------------------------------
#define STB        24576
#define GEMM_SMEM  (4 * STB + 4096)

template <bool TANH>
__global__ void __launch_bounds__(256, 2) gemm_fp16x2(
    const __half* __restrict__ A, const __half* __restrict__ Bm,
    const float* __restrict__ bias, __half* __restrict__ Hout,
    const float* __restrict__ Enc, const int* __restrict__ lengths,
    float* __restrict__ pm, float* __restrict__ ps, float* __restrict__ pa)
{
    extern __shared__ char smem[];
    const uint32_t sbase = s2u(smem);
    const int tid  = threadIdx.x;
    const int wid  = tid >> 5, lane = tid & 31;
    const int bm = blockIdx.y * 128, bn = blockIdx.x * 128;
    const int wm = (wid >> 2) * 64, wn = (wid & 3) * 32;

    // ldmatrix invariants
    const uint32_t xm   = (uint32_t)(lane & 7);                 // B swizzle key
    const uint32_t xa   = (uint32_t)(((lane & 15) >> 1) & 3);   // A swizzle key
    const uint32_t rowA = (uint32_t)(wm + (lane & 15)) * 64;    // A: 64B rows
    const uint32_t rowB = (uint32_t)(wn + (lane & 7) + ((lane >> 4) & 1) * 8) * 128;
    const int cA0 = (lane >> 4);         // A k-group low bit
    const int cB0 = ((lane >> 3) & 1);   // B k-group low bit

    float acc[4][4][4];
    #pragma unroll
    for (int i = 0; i < 4; i++)
        #pragma unroll
        for (int j = 0; j < 4; j++)
            #pragma unroll
            for (int q = 0; q < 4; q++) acc[i][j][q] = 0.0f;

    // cp.async invariants
    // A: 512 16B-chunks (128 rows x 4), 2/thread: rows tid>>2 and +64.
    const int arow = tid >> 2, ac = tid & 3;
    const __half* AgA = A + (size_t)(bm + arow) * 512 + ac * 8;
    const uint32_t soffA = (uint32_t)(arow * 64 + ((ac ^ ((arow >> 1) & 3)) << 4));
    // B: 1024 chunks (128 rows x 8), 4/thread: rows tid>>3 + 32i.
    const int brow = tid >> 3, bc = tid & 7;
    const __half* BgB = Bm + (size_t)(bn + brow) * ROWB + bc * 8;
    const uint32_t soffB = (uint32_t)(brow * 128 + ((bc ^ (brow & 7)) << 4));

    auto load_stage = [&](int kc, int buf) {
        const uint32_t sA = sbase + (uint32_t)buf * STB;
        const uint32_t sB = sA + 8192;
        cp16(sA + soffA,        AgA + kc * 32);
        cp16(sA + soffA + 4096, AgA + (size_t)64 * 512 + kc * 32);
        #pragma unroll
        for (int i = 0; i < 4; i++)
            cp16(sB + soffB + i * 4096, BgB + (size_t)i * 32 * ROWB + kc * 64);
    };

    auto compute_stage = [&](int buf) {
        const uint32_t sA = sbase + (uint32_t)buf * STB;
        const uint32_t sB = sA + 8192;
        #pragma unroll
        for (int s = 0; s < 2; s++) {
            const uint32_t ca = (uint32_t)(s * 2 + cA0);
            const uint32_t cb = (uint32_t)(s * 2 + cB0);
            uint32_t aF[4][4];
            #pragma unroll
            for (int mt = 0; mt < 4; mt++)
                ldsm4(aF[mt], sA + rowA + mt * 1024 + ((ca ^ xa) << 4));
            uint32_t bH[4][2];
            #pragma unroll
            for (int np = 0; np < 2; np++) {
                uint32_t t[4];
                ldsm4(t, sB + rowB + np * 2048 + ((cb ^ xm) << 4));
                bH[np * 2 + 0][0] = t[0]; bH[np * 2 + 0][1] = t[1];
                bH[np * 2 + 1][0] = t[2]; bH[np * 2 + 1][1] = t[3];
            }
            #pragma unroll
            for (int mt = 0; mt < 4; mt++)
                #pragma unroll
                for (int nt = 0; nt < 4; nt++)
                    mma16816h(acc[mt][nt], aF[mt], bH[nt]);
            {   // aF * bL
                uint32_t bL[4][2];
                #pragma unroll
                for (int np = 0; np < 2; np++) {
                    uint32_t t[4];
                    ldsm4(t, sB + rowB + np * 2048 + (((cb + 4) ^ xm) << 4));
                    bL[np * 2 + 0][0] = t[0]; bL[np * 2 + 0][1] = t[1];
                    bL[np * 2 + 1][0] = t[2]; bL[np * 2 + 1][1] = t[3];
                }
                #pragma unroll
                for (int mt = 0; mt < 4; mt++)
                    #pragma unroll
                    for (int nt = 0; nt < 4; nt++)
                        mma16816h(acc[mt][nt], aF[mt], bL[nt]);
            }
        }
    };

    // 4-stage pipeline, fully unrolled.
    load_stage(0, 0);
    asm volatile("cp.async.commit_group;" ::: "memory");
    load_stage(1, 1);
    asm volatile("cp.async.commit_group;" ::: "memory");
    load_stage(2, 2);
    asm volatile("cp.async.commit_group;" ::: "memory");

    #pragma unroll
    for (int kc = 0; kc < 16; kc++) {
        asm volatile("cp.async.wait_group 2;" ::: "memory");
        __syncthreads();            // stage kc visible; stage (kc+3)&3 free
        if (kc + 3 < 16)
            load_stage(kc + 3, (kc + 3) & 3);
        asm volatile("cp.async.commit_group;" ::: "memory");
        compute_stage(kc & 3);
    }

    const int gp = lane >> 2, tg = lane & 3;

    if (TANH) {
        // --- GEMM1 epilogue: bias+tanh -> fp16, smem-staged coalesced out.
        //     smem tile: 128 rows x 256B, 16B-granule swizzle key (r&15). ---
        __syncthreads();   // drain pipeline readers before smem reuse
        #pragma unroll
        for (int mt = 0; mt < 4; mt++) {
            #pragma unroll
            for (int nt = 0; nt < 4; nt++) {
                const int ln = wn + nt * 8 + tg * 2;
                const float b0 = __ldg(bias + bn + ln);
                const float b1 = __ldg(bias + bn + ln + 1);
                #pragma unroll
                for (int rp = 0; rp < 2; rp++) {
                    const int r = wm + mt * 16 + gp + rp * 8;
                    const float d0 = fast_tanh(acc[mt][nt][rp * 2 + 0] + b0);
                    const float d1 = fast_tanh(acc[mt][nt][rp * 2 + 1] + b1);
                    const __half2 hp = __floats2half2_rn(d0, d1);
                    const uint32_t sw = (uint32_t)((ln >> 3) ^ (r & 15));
                    *reinterpret_cast<__half2*>(
                        smem + r * 256 + (sw << 4) + (ln & 7) * 2) = hp;
                }
            }
        }
        __syncthreads();
        // Coalesced copy-out: 32KB = 2048 x 16B; 256B contiguous per row.
        __half* dsth = Hout + (size_t)bm * 512 + bn;
        #pragma unroll
        for (int i = 0; i < 8; i++) {
            const int id  = tid + i * 256;        // 0..2047
            const int row = id >> 4;
            const int c   = id & 15;
            const uint32_t sw = (uint32_t)(c ^ (row & 15));
            const uint4 v = *reinterpret_cast<uint4*>(smem + row * 256 + (sw << 4));
            *reinterpret_cast<uint4*>(dsth + (size_t)row * 512 + c * 8) = v;
        }
    } else {
        // --- GEMM2 fused epilogue: masked softmax partials over 128 rows ---
        const int batch = bm >> 11;
        const int l0    = bm & 2047;
        const int chunk = l0 >> 7;
        const int len   = lengths[batch];

        __syncthreads();   // drain pipeline readers before smem reuse

        // enc fp32 tile [128 x 128] into smem[0..64KB), 16B swizzle (row&7).
        const float* Eg = Enc + (size_t)bm * EDIM + bn;
        #pragma unroll
        for (int i = 0; i < 16; i++) {
            const int id  = tid + i * 256;
            const int row = id >> 5, ch = id & 31;
            const uint32_t off = (uint32_t)(row * 512 + ((ch ^ (row & 7)) << 4));
            cp16(sbase + off, Eg + (size_t)row * EDIM + ch * 4);
        }
        asm volatile("cp.async.commit_group;" ::: "memory");
        asm volatile("cp.async.wait_group 0;" ::: "memory");
        __syncthreads();

        // Phase A: per-column max (sentinel -1e30)
        float M[8];
        #pragma unroll
        for (int ci = 0; ci < 8; ci++) M[ci] = -1e30f;
        #pragma unroll
        for (int mt = 0; mt < 4; mt++)
            #pragma unroll
            for (int rp = 0; rp < 2; rp++) {
                const int lr = wm + mt * 16 + gp + rp * 8;
                const bool valid = (l0 + lr) < len;
                #pragma unroll
                for (int nt = 0; nt < 4; nt++)
                    #pragma unroll
                    for (int j = 0; j < 2; j++) {
                        const float x = valid ? acc[mt][nt][rp * 2 + j] : -1e30f;
                        M[nt * 2 + j] = fmaxf(M[nt * 2 + j], x);
                    }
            }
        #pragma unroll
        for (int ci = 0; ci < 8; ci++) {
            M[ci] = fmaxf(M[ci], __shfl_xor_sync(0xFFFFFFFFu, M[ci], 4));
            M[ci] = fmaxf(M[ci], __shfl_xor_sync(0xFFFFFFFFu, M[ci], 8));
            M[ci] = fmaxf(M[ci], __shfl_xor_sync(0xFFFFFFFFu, M[ci], 16));
        }
        float* smax = reinterpret_cast<float*>(smem + 4 * STB);  // [8][32]
        if (gp == 0) {
            #pragma unroll
            for (int ci = 0; ci < 8; ci++) {
                const int col = (ci >> 1) * 8 + tg * 2 + (ci & 1);
                smax[wid * 32 + col] = M[ci];
            }
        }
        __syncthreads();
        #pragma unroll
        for (int ci = 0; ci < 8; ci++) {
            const int col = (ci >> 1) * 8 + tg * 2 + (ci & 1);
            M[ci] = fmaxf(M[ci], smax[(wid ^ 4) * 32 + col]);
        }

        // Phase B: Σ exp(x-M), Σ exp(x-M)·enc
        float S[8], Aa[8];
        #pragma unroll
        for (int ci = 0; ci < 8; ci++) { S[ci] = 0.0f; Aa[ci] = 0.0f; }
        #pragma unroll
        for (int mt = 0; mt < 4; mt++)
            #pragma unroll
            for (int rp = 0; rp < 2; rp++) {
                const int lr = wm + mt * 16 + gp + rp * 8;
                const bool valid = (l0 + lr) < len;
                #pragma unroll
                for (int nt = 0; nt < 4; nt++) {
                    const int n0 = wn + nt * 8 + tg * 2;
                    const uint32_t eoff = (uint32_t)(lr * 512 +
                        (((n0 >> 2) ^ (lr & 7)) << 4) + (n0 & 3) * 4);
                    const float2 ev =
                        *reinterpret_cast<const float2*>(smem + eoff);
                    #pragma unroll
                    for (int j = 0; j < 2; j++) {
                        const float x = valid ? acc[mt][nt][rp * 2 + j] : -1e30f;
                        const float p = __expf(x - M[nt * 2 + j]);
                        S [nt * 2 + j] += p;
                        Aa[nt * 2 + j] += p * (j ? ev.y : ev.x);
                    }
                }
            }
        #pragma unroll
        for (int ci = 0; ci < 8; ci++) {
            #pragma unroll
            for (int msk = 4; msk <= 16; msk <<= 1) {
                S [ci] += __shfl_xor_sync(0xFFFFFFFFu, S [ci], msk);
                Aa[ci] += __shfl_xor_sync(0xFFFFFFFFu, Aa[ci], msk);
            }
        }
        float* ssum = smax + 256;   // [4 warps][32 cols][2]
        if (wid < 4 && gp == 0) {
            #pragma unroll
            for (int ci = 0; ci < 8; ci++) {
                const int col = (ci >> 1) * 8 + tg * 2 + (ci & 1);
                ssum[(wid * 32 + col) * 2 + 0] = S[ci];
                ssum[(wid * 32 + col) * 2 + 1] = Aa[ci];
            }
        }
        __syncthreads();
        if (wid >= 4 && gp == 0) {
            const size_t base = ((size_t)batch * NCH2 + chunk) * EDIM + bn + wn;
            #pragma unroll
            for (int ci = 0; ci < 8; ci++) {
                const int col = (ci >> 1) * 8 + tg * 2 + (ci & 1);
                pm[base + col] = M[ci];
                ps[base + col] = S[ci]  + ssum[((wid - 4) * 32 + col) * 2 + 0];
                pa[base + col] = Aa[ci] + ssum[((wid - 4) * 32 + col) * 2 + 1];
            }
        }
    }
}

// ---------------------------------------------------------------------------
// Merge NCH2 partials -> out[b][e].
// ---------------------------------------------------------------------------
__global__ __launch_bounds__(512) void softmax_merge(
    const float* __restrict__ pm, const float* __restrict__ ps,
    const float* __restrict__ pa, float* __restrict__ out)
{
    const int b = blockIdx.x, e = threadIdx.x;
    float M = -1e30f;
    #pragma unroll 4
    for (int c = 0; c < NCH2; c++)
        M = fmaxf(M, pm[((size_t)b * NCH2 + c) * EDIM + e]);
    float S = 0.0f, Acc = 0.0f;
    #pragma unroll 4
    for (int c = 0; c < NCH2; c++) {
        const size_t o = ((size_t)b * NCH2 + c) * EDIM + e;
        const float w = __expf(pm[o] - M);
        S   += ps[o] * w;
        Acc += pa[o] * w;
    }
    out[(size_t)b * EDIM + e] = Acc / S;
}

// ---------------------------------------------------------------------------
// Inputs: encodings [B,L,E] f32, lengths [B] i32, W_h [E,H] f32,
//         b_h [H] f32, W_c [H,E] f32. Output: [B,1,E] f32.
// ---------------------------------------------------------------------------
extern "C" void kernel_launch(void* const* d_in, const int* in_sizes, int n_in,
                              void* d_out, int out_size)
{
    const float* enc = (const float*)d_in[0];
    const int*   len = (const int*)  d_in[1];
    const float* W_h = (const float*)d_in[2];
    const float* b_h = (const float*)d_in[3];
    const float* W_c = (const float*)d_in[4];
    float* out = (float*)d_out;

    __half *encF, *hF, *WhHL, *WcHL;
    float *pm, *ps, *pa;
    cudaGetSymbolAddress((void**)&encF, g_encF);
    cudaGetSymbolAddress((void**)&hF,   g_hF);
    cudaGetSymbolAddress((void**)&WhHL, g_WhHL);
    cudaGetSymbolAddress((void**)&WcHL, g_WcHL);
    cudaGetSymbolAddress((void**)&pm,   g_pm);
    cudaGetSymbolAddress((void**)&ps,   g_ps);
    cudaGetSymbolAddress((void**)&pa,   g_pa);

    cudaFuncSetAttribute(gemm_fp16x2<true>,
        cudaFuncAttributeMaxDynamicSharedMemorySize, GEMM_SMEM);
    cudaFuncSetAttribute(gemm_fp16x2<false>,
        cudaFuncAttributeMaxDynamicSharedMemorySize, GEMM_SMEM);

    convert_A<<<(MTOT * 64) / 256, 256>>>(enc, encF);
    dim3 gw((512 * 512) / 256, 2);
    convert_W<<<gw, 256>>>(W_h, W_c, WhHL, WcHL);

    dim3 gg(4, MTOT / 128);   // (N/128, M/128)
    gemm_fp16x2<true ><<<gg, 256, GEMM_SMEM>>>(
        encF, WhHL, b_h, hF, nullptr, nullptr, nullptr, nullptr, nullptr);
    gemm_fp16x2<false><<<gg, 256, GEMM_SMEM>>>(
        hF, WcHL, nullptr, nullptr, enc, len, pm, ps, pa);

    softmax_merge<<<BATCH, EDIM>>>(pm, ps, pa, out);
}

// round 10
// speedup vs baseline: 6.0618x; 1.2186x over previous
#include <cuda_runtime.h>
#include <cuda_fp16.h>
#include <math.h>
#include <stdint.h>

// Problem constants
#define BATCH 32
#define SEQL  2048
#define EDIM  512
#define HDIM  512
#define KDIM  512
#define MTOT  (BATCH * SEQL)     // 65536
#define NCH2  16                 // softmax chunks = 2048/128
#define ROWB  1024               // fp16 elems per HL B n-row: (512/32)*64

// A operands: plain fp16 row-major [M][512].
// W_h: HL fp16 [n][k...] (2-pass GEMM1). W_c: plain fp16 [n][512] (1-pass).
__device__ __half g_encF[(size_t)MTOT * 512];
__device__ __half g_hF  [(size_t)MTOT * 512];
__device__ __half g_WhHL[(size_t)HDIM * ROWB];
__device__ __half g_WcF [(size_t)EDIM * 512];
__device__ float g_pm [BATCH * NCH2 * EDIM];
__device__ float g_ps [BATCH * NCH2 * EDIM];
__device__ float g_pa [BATCH * NCH2 * EDIM];

// ---------------------------------------------------------------------------
// helpers
// ---------------------------------------------------------------------------
__device__ __forceinline__ uint32_t s2u(const void* p) {
    uint32_t a;
    asm("{ .reg .u64 t; cvta.to.shared.u64 t, %1; cvt.u32.u64 %0, t; }"
        : "=r"(a) : "l"(p));
    return a;
}
__device__ __forceinline__ void cp16(uint32_t dst, const void* src) {
    asm volatile("cp.async.cg.shared.global [%0], [%1], 16;"
                 :: "r"(dst), "l"(src) : "memory");
}
__device__ __forceinline__ void ldsm4(uint32_t* r, uint32_t addr) {
    asm volatile("ldmatrix.sync.aligned.m8n8.x4.shared.b16 {%0,%1,%2,%3}, [%4];"
                 : "=r"(r[0]), "=r"(r[1]), "=r"(r[2]), "=r"(r[3]) : "r"(addr));
}
__device__ __forceinline__ void mma16816h(float* d, const uint32_t* a,
                                          const uint32_t* b) {
    asm volatile(
        "mma.sync.aligned.m16n8k16.row.col.f32.f16.f16.f32 "
        "{%0,%1,%2,%3},{%4,%5,%6,%7},{%8,%9},{%0,%1,%2,%3};"
        : "+f"(d[0]), "+f"(d[1]), "+f"(d[2]), "+f"(d[3])
        : "r"(a[0]), "r"(a[1]), "r"(a[2]), "r"(a[3]), "r"(b[0]), "r"(b[1]));
}
// fast tanh: (e^{2x}-1)/(e^{2x}+1), clamp avoids inf/inf; err ~1e-6.
__device__ __forceinline__ float fast_tanh(float x) {
    x = fminf(fmaxf(x, -15.0f), 15.0f);
    const float e = __expf(2.0f * x);
    return __fdividef(e - 1.0f, e + 1.0f);
}

// ---------------------------------------------------------------------------
// convert encodings fp32 [M][512] -> plain fp16. 8 elems/thread, 16B store.
// ---------------------------------------------------------------------------
__global__ __launch_bounds__(256) void convert_A(
    const float* __restrict__ src, __half* __restrict__ dst)
{
    const size_t g = (size_t)blockIdx.x * 256 + threadIdx.x;   // M*64 threads
    const int m = (int)(g >> 6);
    const int k = (int)(g & 63) * 8;
    const float4 v0 = *reinterpret_cast<const float4*>(src + (size_t)m * KDIM + k);
    const float4 v1 = *reinterpret_cast<const float4*>(src + (size_t)m * KDIM + k + 4);
    __half2 h[4];
    h[0] = __floats2half2_rn(v0.x, v0.y);
    h[1] = __floats2half2_rn(v0.z, v0.w);
    h[2] = __floats2half2_rn(v1.x, v1.y);
    h[3] = __floats2half2_rn(v1.z, v1.w);
    *reinterpret_cast<uint4*>(dst + (size_t)m * 512 + k) =
        *reinterpret_cast<uint4*>(h);
}

// ---------------------------------------------------------------------------
// convert W: W_h fp32 [K][N] -> N-major HL fp16; W_c fp32 [K][N] -> N-major
// plain fp16 [n][k].
// ---------------------------------------------------------------------------
__global__ __launch_bounds__(256) void convert_W(
    const float* __restrict__ Wh, const float* __restrict__ Wc,
    __half* __restrict__ dhl, __half* __restrict__ dcf)
{
    const int g = blockIdx.x * 256 + threadIdx.x;   // 512*512 threads
    const int k = g >> 9;
    const int n = g & 511;
    if (blockIdx.y == 0) {
        const float w = Wh[(size_t)k * 512 + n];
        const __half h = __float2half_rn(w);
        const __half l = __float2half_rn(w - __half2float(h));
        __half* p = dhl + (size_t)n * ROWB + (k >> 5) * 64 + (k & 31);
        p[0]  = h;
        p[32] = l;
    } else {
        dcf[(size_t)n * 512 + k] = __float2half_rn(Wc[(size_t)k * 512 + n]);
    }
}

// ---------------------------------------------------------------------------
// fp16 tensor-core GEMM. CTA tile 128x128, 8 warps (2m x 4n), warp 64x32,
// k=32/stage, 4-stage cp.async pipeline, fully unrolled, 2 CTAs/SM.
// PASSES=2 (GEMM1): B in HL layout (16KB/stage), C += A*(bH+bL);
//                   epilogue bias+tanh -> plain fp16 via smem staging.
// PASSES=1 (GEMM2): B plain fp16 (8KB/stage), single pass;
//                   fused masked-softmax partial epilogue.
// ---------------------------------------------------------------------------
template <int PASSES> struct StageCfg;
template <> struct StageCfg<2> { static constexpr int STB = 24576; };
template <> struct StageCfg<1> { static constexpr int STB = 16384; };
#define GEMM_SMEM(P) (4 * StageCfg<P>::STB + 4096)

template <int PASSES>
__global__ void __launch_bounds__(256, 2) gemm_fp16(
    const __half* __restrict__ A, const __half* __restrict__ Bm,
    const float* __restrict__ bias, __half* __restrict__ Hout,
    const float* __restrict__ Enc, const int* __restrict__ lengths,
    float* __restrict__ pm, float* __restrict__ ps, float* __restrict__ pa)
{
    constexpr int STB = StageCfg<PASSES>::STB;
    extern __shared__ char smem[];
    const uint32_t sbase = s2u(smem);
    const int tid  = threadIdx.x;
    const int wid  = tid >> 5, lane = tid & 31;
    const int bm = blockIdx.y * 128, bn = blockIdx.x * 128;
    const int wm = (wid >> 2) * 64, wn = (wid & 3) * 32;

    // ldmatrix invariants
    const uint32_t xa   = (uint32_t)(((lane & 15) >> 1) & 3);   // 64B-row key
    const uint32_t rowA = (uint32_t)(wm + (lane & 15)) * 64;
    const int cA0 = (lane >> 4);
    const int cB0 = ((lane >> 3) & 1);
    // B row base: HL rows are 128B; plain rows are 64B.
    const uint32_t laneR = (uint32_t)((lane & 7) + ((lane >> 4) & 1) * 8);
    const uint32_t xmHL  = (uint32_t)(lane & 7);
    const uint32_t rowBHL = (uint32_t)(wn + (int)laneR) * 128;
    const uint32_t xb1    = (laneR >> 1) & 3;
    const uint32_t rowB1  = (uint32_t)(wn + (int)laneR) * 64;

    float acc[4][4][4];
    #pragma unroll
    for (int i = 0; i < 4; i++)
        #pragma unroll
        for (int j = 0; j < 4; j++)
            #pragma unroll
            for (int q = 0; q < 4; q++) acc[i][j][q] = 0.0f;

    // cp.async invariants
    // A: 512 16B-chunks (128 rows x 4), 2/thread.
    const int arow = tid >> 2, ac = tid & 3;
    const __half* AgA = A + (size_t)(bm + arow) * 512 + ac * 8;
    const uint32_t soffA = (uint32_t)(arow * 64 + ((ac ^ ((arow >> 1) & 3)) << 4));
    // B(HL): 1024 chunks (128 rows x 8), 4/thread.
    const int brow = tid >> 3, bc = tid & 7;
    const __half* BgHL = Bm + (size_t)(bn + brow) * ROWB + bc * 8;
    const uint32_t soffBHL = (uint32_t)(brow * 128 + ((bc ^ (brow & 7)) << 4));
    // B(plain): same shape as A.
    const __half* BgF = Bm + (size_t)(bn + arow) * 512 + ac * 8;

    auto load_stage = [&](int kc, int buf) {
        const uint32_t sA = sbase + (uint32_t)buf * STB;
        const uint32_t sB = sA + 8192;
        cp16(sA + soffA,        AgA + kc * 32);
        cp16(sA + soffA + 4096, AgA + (size_t)64 * 512 + kc * 32);
        if (PASSES == 2) {
            #pragma unroll
            for (int i = 0; i < 4; i++)
                cp16(sB + soffBHL + i * 4096, BgHL + (size_t)i * 32 * ROWB + kc * 64);
        } else {
            cp16(sB + soffA,        BgF + kc * 32);
            cp16(sB + soffA + 4096, BgF + (size_t)64 * 512 + kc * 32);
        }
    };

    auto compute_stage = [&](int buf) {
        const uint32_t sA = sbase + (uint32_t)buf * STB;
        const uint32_t sB = sA + 8192;
        #pragma unroll
        for (int s = 0; s < 2; s++) {
            const uint32_t ca = (uint32_t)(s * 2 + cA0);
            const uint32_t cb = (uint32_t)(s * 2 + cB0);
            uint32_t aF[4][4];
            #pragma unroll
            for (int mt = 0; mt < 4; mt++)
                ldsm4(aF[mt], sA + rowA + mt * 1024 + ((ca ^ xa) << 4));
            uint32_t bF[4][2];
            #pragma unroll
            for (int np = 0; np < 2; np++) {
                uint32_t t[4];
                if (PASSES == 2)
                    ldsm4(t, sB + rowBHL + np * 2048 + ((cb ^ xmHL) << 4));
                else
                    ldsm4(t, sB + rowB1 + np * 1024 + ((cb ^ xb1) << 4));
                bF[np * 2 + 0][0] = t[0]; bF[np * 2 + 0][1] = t[1];
                bF[np * 2 + 1][0] = t[2]; bF[np * 2 + 1][1] = t[3];
            }
            #pragma unroll
            for (int mt = 0; mt < 4; mt++)
                #pragma unroll
                for (int nt = 0; nt < 4; nt++)
                    mma16816h(acc[mt][nt], aF[mt], bF[nt]);
            if (PASSES == 2) {   // aF * bL
                uint32_t bL[4][2];
                #pragma unroll
                for (int np = 0; np < 2; np++) {
                    uint32_t t[4];
                    ldsm4(t, sB + rowBHL + np * 2048 + (((cb + 4) ^ xmHL) << 4));
                    bL[np * 2 + 0][0] = t[0]; bL[np * 2 + 0][1] = t[1];
                    bL[np * 2 + 1][0] = t[2]; bL[np * 2 + 1][1] = t[3];
                }
                #pragma unroll
                for (int mt = 0; mt < 4; mt++)
                    #pragma unroll
                    for (int nt = 0; nt < 4; nt++)
                        mma16816h(acc[mt][nt], aF[mt], bL[nt]);
            }
        }
    };

    // 4-stage pipeline, fully unrolled.
    load_stage(0, 0);
    asm volatile("cp.async.commit_group;" ::: "memory");
    load_stage(1, 1);
    asm volatile("cp.async.commit_group;" ::: "memory");
    load_stage(2, 2);
    asm volatile("cp.async.commit_group;" ::: "memory");

    #pragma unroll
    for (int kc = 0; kc < 16; kc++) {
        asm volatile("cp.async.wait_group 2;" ::: "memory");
        __syncthreads();            // stage kc visible; stage (kc+3)&3 free
        if (kc + 3 < 16)
            load_stage(kc + 3, (kc + 3) & 3);
        asm volatile("cp.async.commit_group;" ::: "memory");
        compute_stage(kc & 3);
    }

    const int gp = lane >> 2, tg = lane & 3;

    if (PASSES == 2) {
        // --- GEMM1 epilogue: bias+tanh -> fp16, smem-staged coalesced out ---
        __syncthreads();   // drain pipeline readers before smem reuse
        #pragma unroll
        for (int mt = 0; mt < 4; mt++) {
            #pragma unroll
            for (int nt = 0; nt < 4; nt++) {
                const int ln = wn + nt * 8 + tg * 2;
                const float b0 = __ldg(bias + bn + ln);
                const float b1 = __ldg(bias + bn + ln + 1);
                #pragma unroll
                for (int rp = 0; rp < 2; rp++) {
                    const int r = wm + mt * 16 + gp + rp * 8;
                    const float d0 = fast_tanh(acc[mt][nt][rp * 2 + 0] + b0);
                    const float d1 = fast_tanh(acc[mt][nt][rp * 2 + 1] + b1);
                    const __half2 hp = __floats2half2_rn(d0, d1);
                    const uint32_t sw = (uint32_t)((ln >> 3) ^ (r & 15));
                    *reinterpret_cast<__half2*>(
                        smem + r * 256 + (sw << 4) + (ln & 7) * 2) = hp;
                }
            }
        }
        __syncthreads();
        __half* dsth = Hout + (size_t)bm * 512 + bn;
        #pragma unroll
        for (int i = 0; i < 8; i++) {
            const int id  = tid + i * 256;        // 0..2047
            const int row = id >> 4;
            const int c   = id & 15;
            const uint32_t sw = (uint32_t)(c ^ (row & 15));
            const uint4 v = *reinterpret_cast<uint4*>(smem + row * 256 + (sw << 4));
            *reinterpret_cast<uint4*>(dsth + (size_t)row * 512 + c * 8) = v;
        }
    } else {
        // --- GEMM2 fused epilogue: masked softmax partials over 128 rows ---
        const int batch = bm >> 11;
        const int l0    = bm & 2047;
        const int chunk = l0 >> 7;
        const int len   = lengths[batch];

        __syncthreads();   // drain pipeline readers before smem reuse

        // enc fp32 tile [128 x 128] into smem[0..64KB), 16B swizzle (row&7).
        const float* Eg = Enc + (size_t)bm * EDIM + bn;
        #pragma unroll
        for (int i = 0; i < 16; i++) {
            const int id  = tid + i * 256;
            const int row = id >> 5, ch = id & 31;
            const uint32_t off = (uint32_t)(row * 512 + ((ch ^ (row & 7)) << 4));
            cp16(sbase + off, Eg + (size_t)row * EDIM + ch * 4);
        }
        asm volatile("cp.async.commit_group;" ::: "memory");
        asm volatile("cp.async.wait_group 0;" ::: "memory");
        __syncthreads();

        // Phase A: per-column max (sentinel -1e30)
        float M[8];
        #pragma unroll
        for (int ci = 0; ci < 8; ci++) M[ci] = -1e30f;
        #pragma unroll
        for (int mt = 0; mt < 4; mt++)
            #pragma unroll
            for (int rp = 0; rp < 2; rp++) {
                const int lr = wm + mt * 16 + gp + rp * 8;
                const bool valid = (l0 + lr) < len;
                #pragma unroll
                for (int nt = 0; nt < 4; nt++)
                    #pragma unroll
                    for (int j = 0; j < 2; j++) {
                        const float x = valid ? acc[mt][nt][rp * 2 + j] : -1e30f;
                        M[nt * 2 + j] = fmaxf(M[nt * 2 + j], x);
                    }
            }
        #pragma unroll
        for (int ci = 0; ci < 8; ci++) {
            M[ci] = fmaxf(M[ci], __shfl_xor_sync(0xFFFFFFFFu, M[ci], 4));
            M[ci] = fmaxf(M[ci], __shfl_xor_sync(0xFFFFFFFFu, M[ci], 8));
            M[ci] = fmaxf(M[ci], __shfl_xor_sync(0xFFFFFFFFu, M[ci], 16));
        }
        float* smax = reinterpret_cast<float*>(smem + 4 * STB);  // [8][32]
        if (gp == 0) {
            #pragma unroll
            for (int ci = 0; ci < 8; ci++) {
                const int col = (ci >> 1) * 8 + tg * 2 + (ci & 1);
                smax[wid * 32 + col] = M[ci];
            }
        }
        __syncthreads();
        #pragma unroll
        for (int ci = 0; ci < 8; ci++) {
            const int col = (ci >> 1) * 8 + tg * 2 + (ci & 1);
            M[ci] = fmaxf(M[ci], smax[(wid ^ 4) * 32 + col]);
        }

        // Phase B: Σ exp(x-M), Σ exp(x-M)·enc
        float S[8], Aa[8];
        #pragma unroll
        for (int ci = 0; ci < 8; ci++) { S[ci] = 0.0f; Aa[ci] = 0.0f; }
        #pragma unroll
        for (int mt = 0; mt < 4; mt++)
            #pragma unroll
            for (int rp = 0; rp < 2; rp++) {
                const int lr = wm + mt * 16 + gp + rp * 8;
                const bool valid = (l0 + lr) < len;
                #pragma unroll
                for (int nt = 0; nt < 4; nt++) {
                    const int n0 = wn + nt * 8 + tg * 2;
                    const uint32_t eoff = (uint32_t)(lr * 512 +
                        (((n0 >> 2) ^ (lr & 7)) << 4) + (n0 & 3) * 4);
                    const float2 ev =
                        *reinterpret_cast<const float2*>(smem + eoff);
                    #pragma unroll
                    for (int j = 0; j < 2; j++) {
                        const float x = valid ? acc[mt][nt][rp * 2 + j] : -1e30f;
                        const float p = __expf(x - M[nt * 2 + j]);
                        S [nt * 2 + j] += p;
                        Aa[nt * 2 + j] += p * (j ? ev.y : ev.x);
                    }
                }
            }
        #pragma unroll
        for (int ci = 0; ci < 8; ci++) {
            #pragma unroll
            for (int msk = 4; msk <= 16; msk <<= 1) {
                S [ci] += __shfl_xor_sync(0xFFFFFFFFu, S [ci], msk);
                Aa[ci] += __shfl_xor_sync(0xFFFFFFFFu, Aa[ci], msk);
            }
        }
        float* ssum = smax + 256;   // [4 warps][32 cols][2]
        if (wid < 4 && gp == 0) {
            #pragma unroll
            for (int ci = 0; ci < 8; ci++) {
                const int col = (ci >> 1) * 8 + tg * 2 + (ci & 1);
                ssum[(wid * 32 + col) * 2 + 0] = S[ci];
                ssum[(wid * 32 + col) * 2 + 1] = Aa[ci];
            }
        }
        __syncthreads();
        if (wid >= 4 && gp == 0) {
            const size_t base = ((size_t)batch * NCH2 + chunk) * EDIM + bn + wn;
            #pragma unroll
            for (int ci = 0; ci < 8; ci++) {
                const int col = (ci >> 1) * 8 + tg * 2 + (ci & 1);
                pm[base + col] = M[ci];
                ps[base + col] = S[ci]  + ssum[((wid - 4) * 32 + col) * 2 + 0];
                pa[base + col] = Aa[ci] + ssum[((wid - 4) * 32 + col) * 2 + 1];
            }
        }
    }
}

// ---------------------------------------------------------------------------
// Merge NCH2 partials -> out[b][e].
// ---------------------------------------------------------------------------
__global__ __launch_bounds__(512) void softmax_merge(
    const float* __restrict__ pm, const float* __restrict__ ps,
    const float* __restrict__ pa, float* __restrict__ out)
{
    const int b = blockIdx.x, e = threadIdx.x;
    float M = -1e30f;
    #pragma unroll 4
    for (int c = 0; c < NCH2; c++)
        M = fmaxf(M, pm[((size_t)b * NCH2 + c) * EDIM + e]);
    float S = 0.0f, Acc = 0.0f;
    #pragma unroll 4
    for (int c = 0; c < NCH2; c++) {
        const size_t o = ((size_t)b * NCH2 + c) * EDIM + e;
        const float w = __expf(pm[o] - M);
        S   += ps[o] * w;
        Acc += pa[o] * w;
    }
    out[(size_t)b * EDIM + e] = Acc / S;
}

// ---------------------------------------------------------------------------
// Inputs: encodings [B,L,E] f32, lengths [B] i32, W_h [E,H] f32,
//         b_h [H] f32, W_c [H,E] f32. Output: [B,1,E] f32.
// ---------------------------------------------------------------------------
extern "C" void kernel_launch(void* const* d_in, const int* in_sizes, int n_in,
                              void* d_out, int out_size)
{
    const float* enc = (const float*)d_in[0];
    const int*   len = (const int*)  d_in[1];
    const float* W_h = (const float*)d_in[2];
    const float* b_h = (const float*)d_in[3];
    const float* W_c = (const float*)d_in[4];
    float* out = (float*)d_out;

    __half *encF, *hF, *WhHL, *WcF;
    float *pm, *ps, *pa;
    cudaGetSymbolAddress((void**)&encF, g_encF);
    cudaGetSymbolAddress((void**)&hF,   g_hF);
    cudaGetSymbolAddress((void**)&WhHL, g_WhHL);
    cudaGetSymbolAddress((void**)&WcF,  g_WcF);
    cudaGetSymbolAddress((void**)&pm,   g_pm);
    cudaGetSymbolAddress((void**)&ps,   g_ps);
    cudaGetSymbolAddress((void**)&pa,   g_pa);

    cudaFuncSetAttribute(gemm_fp16<2>,
        cudaFuncAttributeMaxDynamicSharedMemorySize, GEMM_SMEM(2));
    cudaFuncSetAttribute(gemm_fp16<1>,
        cudaFuncAttributeMaxDynamicSharedMemorySize, GEMM_SMEM(1));

    convert_A<<<(MTOT * 64) / 256, 256>>>(enc, encF);
    dim3 gw((512 * 512) / 256, 2);
    convert_W<<<gw, 256>>>(W_h, W_c, WhHL, WcF);

    dim3 gg(4, MTOT / 128);   // (N/128, M/128)
    gemm_fp16<2><<<gg, 256, GEMM_SMEM(2)>>>(
        encF, WhHL, b_h, hF, nullptr, nullptr, nullptr, nullptr, nullptr);
    gemm_fp16<1><<<gg, 256, GEMM_SMEM(1)>>>(
        hF, WcF, nullptr, nullptr, enc, len, pm, ps, pa);

    softmax_merge<<<BATCH, EDIM>>>(pm, ps, pa, out);
}

// round 11
// speedup vs baseline: 7.6189x; 1.2569x over previous
#include <cuda_runtime.h>
#include <cuda_fp16.h>
#include <math.h>
#include <stdint.h>

// Problem constants
#define BATCH 32
#define SEQL  2048
#define EDIM  512
#define HDIM  512
#define KDIM  512
#define MTOT  (BATCH * SEQL)     // 65536
#define NCH2  16                 // softmax chunks = 2048/128

// All GEMM operands plain fp16: A row-major [M][512], W N-major [n][512].
__device__ __half g_encF[(size_t)MTOT * 512];
__device__ __half g_hF  [(size_t)MTOT * 512];
__device__ __half g_WhF [(size_t)HDIM * 512];
__device__ __half g_WcF [(size_t)EDIM * 512];
__device__ float g_pm [BATCH * NCH2 * EDIM];
__device__ float g_ps [BATCH * NCH2 * EDIM];
__device__ float g_pa [BATCH * NCH2 * EDIM];

// ---------------------------------------------------------------------------
// helpers
// ---------------------------------------------------------------------------
__device__ __forceinline__ uint32_t s2u(const void* p) {
    uint32_t a;
    asm("{ .reg .u64 t; cvta.to.shared.u64 t, %1; cvt.u32.u64 %0, t; }"
        : "=r"(a) : "l"(p));
    return a;
}
__device__ __forceinline__ void cp16(uint32_t dst, const void* src) {
    asm volatile("cp.async.cg.shared.global [%0], [%1], 16;"
                 :: "r"(dst), "l"(src) : "memory");
}
__device__ __forceinline__ void ldsm4(uint32_t* r, uint32_t addr) {
    asm volatile("ldmatrix.sync.aligned.m8n8.x4.shared.b16 {%0,%1,%2,%3}, [%4];"
                 : "=r"(r[0]), "=r"(r[1]), "=r"(r[2]), "=r"(r[3]) : "r"(addr));
}
__device__ __forceinline__ void mma16816h(float* d, const uint32_t* a,
                                          const uint32_t* b) {
    asm volatile(
        "mma.sync.aligned.m16n8k16.row.col.f32.f16.f16.f32 "
        "{%0,%1,%2,%3},{%4,%5,%6,%7},{%8,%9},{%0,%1,%2,%3};"
        : "+f"(d[0]), "+f"(d[1]), "+f"(d[2]), "+f"(d[3])
        : "r"(a[0]), "r"(a[1]), "r"(a[2]), "r"(a[3]), "r"(b[0]), "r"(b[1]));
}
// fast tanh: (e^{2x}-1)/(e^{2x}+1), clamp avoids inf/inf; err ~1e-6.
__device__ __forceinline__ float fast_tanh(float x) {
    x = fminf(fmaxf(x, -15.0f), 15.0f);
    const float e = __expf(2.0f * x);
    return __fdividef(e - 1.0f, e + 1.0f);
}

// ---------------------------------------------------------------------------
// convert encodings fp32 [M][512] -> plain fp16. 8 elems/thread, 16B store.
// ---------------------------------------------------------------------------
__global__ __launch_bounds__(256) void convert_A(
    const float* __restrict__ src, __half* __restrict__ dst)
{
    const size_t g = (size_t)blockIdx.x * 256 + threadIdx.x;   // M*64 threads
    const int m = (int)(g >> 6);
    const int k = (int)(g & 63) * 8;
    const float4 v0 = *reinterpret_cast<const float4*>(src + (size_t)m * KDIM + k);
    const float4 v1 = *reinterpret_cast<const float4*>(src + (size_t)m * KDIM + k + 4);
    __half2 h[4];
    h[0] = __floats2half2_rn(v0.x, v0.y);
    h[1] = __floats2half2_rn(v0.z, v0.w);
    h[2] = __floats2half2_rn(v1.x, v1.y);
    h[3] = __floats2half2_rn(v1.z, v1.w);
    *reinterpret_cast<uint4*>(dst + (size_t)m * 512 + k) =
        *reinterpret_cast<uint4*>(h);
}

// ---------------------------------------------------------------------------
// convert both W fp32 [K][N] -> N-major plain fp16 [n][k].
// ---------------------------------------------------------------------------
__global__ __launch_bounds__(256) void convert_W(
    const float* __restrict__ Wh, const float* __restrict__ Wc,
    __half* __restrict__ dh, __half* __restrict__ dc)
{
    const float* W = blockIdx.y ? Wc : Wh;
    __half* dst = blockIdx.y ? dc : dh;
    const int g = blockIdx.x * 256 + threadIdx.x;   // 512*512 threads
    const int k = g >> 9;
    const int n = g & 511;
    dst[(size_t)n * 512 + k] = __float2half_rn(W[(size_t)k * 512 + n]);
}

// ---------------------------------------------------------------------------
// Single-pass fp16 tensor-core GEMM: C = A[M,512] @ B[n][512]^T.
// CTA tile 128x128, 8 warps (2m x 4n), warp 64x32, k=32/stage,
// 4-stage cp.async pipeline (16KB/stage), fully unrolled, 2 CTAs/SM.
// TANH=true : bias+tanh -> plain fp16 h via smem-staged coalesced stores.
// TANH=false: fused masked-softmax partial epilogue (att never hits DRAM).
// ---------------------------------------------------------------------------
#define STB        16384
#define GEMM_SMEM  (4 * STB + 4096)

template <bool TANH>
__global__ void __launch_bounds__(256, 2) gemm_fp16(
    const __half* __restrict__ A, const __half* __restrict__ Bm,
    const float* __restrict__ bias, __half* __restrict__ Hout,
    const float* __restrict__ Enc, const int* __restrict__ lengths,
    float* __restrict__ pm, float* __restrict__ ps, float* __restrict__ pa)
{
    extern __shared__ char smem[];
    const uint32_t sbase = s2u(smem);
    const int tid  = threadIdx.x;
    const int wid  = tid >> 5, lane = tid & 31;
    const int bm = blockIdx.y * 128, bn = blockIdx.x * 128;
    const int wm = (wid >> 2) * 64, wn = (wid & 3) * 32;

    // ldmatrix invariants (64B rows, 4-chunk XOR swizzle keyed by (row>>1)&3)
    const uint32_t xa   = (uint32_t)(((lane & 15) >> 1) & 3);
    const uint32_t rowA = (uint32_t)(wm + (lane & 15)) * 64;
    const int cA0 = (lane >> 4);
    const int cB0 = ((lane >> 3) & 1);
    const uint32_t laneR = (uint32_t)((lane & 7) + ((lane >> 4) & 1) * 8);
    const uint32_t xb    = (laneR >> 1) & 3;
    const uint32_t rowB  = (uint32_t)(wn + (int)laneR) * 64;

    float acc[4][4][4];
    #pragma unroll
    for (int i = 0; i < 4; i++)
        #pragma unroll
        for (int j = 0; j < 4; j++)
            #pragma unroll
            for (int q = 0; q < 4; q++) acc[i][j][q] = 0.0f;

    // cp.async invariants: A/B each 512 16B-chunks (128 rows x 4), 2/thread.
    const int arow = tid >> 2, ac = tid & 3;
    const __half* Ag = A  + (size_t)(bm + arow) * 512 + ac * 8;
    const __half* Bg = Bm + (size_t)(bn + arow) * 512 + ac * 8;
    const uint32_t soff = (uint32_t)(arow * 64 + ((ac ^ ((arow >> 1) & 3)) << 4));

    auto load_stage = [&](int kc, int buf) {
        const uint32_t sA = sbase + (uint32_t)buf * STB;
        const uint32_t sB = sA + 8192;
        cp16(sA + soff,        Ag + kc * 32);
        cp16(sA + soff + 4096, Ag + (size_t)64 * 512 + kc * 32);
        cp16(sB + soff,        Bg + kc * 32);
        cp16(sB + soff + 4096, Bg + (size_t)64 * 512 + kc * 32);
    };

    auto compute_stage = [&](int buf) {
        const uint32_t sA = sbase + (uint32_t)buf * STB;
        const uint32_t sB = sA + 8192;
        #pragma unroll
        for (int s = 0; s < 2; s++) {
            const uint32_t ca = (uint32_t)(s * 2 + cA0);
            const uint32_t cb = (uint32_t)(s * 2 + cB0);
            uint32_t aF[4][4];
            #pragma unroll
            for (int mt = 0; mt < 4; mt++)
                ldsm4(aF[mt], sA + rowA + mt * 1024 + ((ca ^ xa) << 4));
            uint32_t bF[4][2];
            #pragma unroll
            for (int np = 0; np < 2; np++) {
                uint32_t t[4];
                ldsm4(t, sB + rowB + np * 1024 + ((cb ^ xb) << 4));
                bF[np * 2 + 0][0] = t[0]; bF[np * 2 + 0][1] = t[1];
                bF[np * 2 + 1][0] = t[2]; bF[np * 2 + 1][1] = t[3];
            }
            #pragma unroll
            for (int mt = 0; mt < 4; mt++)
                #pragma unroll
                for (int nt = 0; nt < 4; nt++)
                    mma16816h(acc[mt][nt], aF[mt], bF[nt]);
        }
    };

    // 4-stage pipeline, fully unrolled.
    load_stage(0, 0);
    asm volatile("cp.async.commit_group;" ::: "memory");
    load_stage(1, 1);
    asm volatile("cp.async.commit_group;" ::: "memory");
    load_stage(2, 2);
    asm volatile("cp.async.commit_group;" ::: "memory");

    #pragma unroll
    for (int kc = 0; kc < 16; kc++) {
        asm volatile("cp.async.wait_group 2;" ::: "memory");
        __syncthreads();            // stage kc visible; stage (kc+3)&3 free
        if (kc + 3 < 16)
            load_stage(kc + 3, (kc + 3) & 3);
        asm volatile("cp.async.commit_group;" ::: "memory");
        compute_stage(kc & 3);
    }

    const int gp = lane >> 2, tg = lane & 3;

    if (TANH) {
        // --- GEMM1 epilogue: bias+tanh -> fp16, smem-staged coalesced out ---
        __syncthreads();   // drain pipeline readers before smem reuse
        #pragma unroll
        for (int mt = 0; mt < 4; mt++) {
            #pragma unroll
            for (int nt = 0; nt < 4; nt++) {
                const int ln = wn + nt * 8 + tg * 2;
                const float b0 = __ldg(bias + bn + ln);
                const float b1 = __ldg(bias + bn + ln + 1);
                #pragma unroll
                for (int rp = 0; rp < 2; rp++) {
                    const int r = wm + mt * 16 + gp + rp * 8;
                    const float d0 = fast_tanh(acc[mt][nt][rp * 2 + 0] + b0);
                    const float d1 = fast_tanh(acc[mt][nt][rp * 2 + 1] + b1);
                    const __half2 hp = __floats2half2_rn(d0, d1);
                    const uint32_t sw = (uint32_t)((ln >> 3) ^ (r & 15));
                    *reinterpret_cast<__half2*>(
                        smem + r * 256 + (sw << 4) + (ln & 7) * 2) = hp;
                }
            }
        }
        __syncthreads();
        __half* dsth = Hout + (size_t)bm * 512 + bn;
        #pragma unroll
        for (int i = 0; i < 8; i++) {
            const int id  = tid + i * 256;        // 0..2047
            const int row = id >> 4;
            const int c   = id & 15;
            const uint32_t sw = (uint32_t)(c ^ (row & 15));
            const uint4 v = *reinterpret_cast<uint4*>(smem + row * 256 + (sw << 4));
            *reinterpret_cast<uint4*>(dsth + (size_t)row * 512 + c * 8) = v;
        }
    } else {
        // --- GEMM2 fused epilogue: masked softmax partials over 128 rows ---
        const int batch = bm >> 11;
        const int l0    = bm & 2047;
        const int chunk = l0 >> 7;
        const int len   = lengths[batch];

        __syncthreads();   // drain pipeline readers before smem reuse

        // enc fp32 tile [128 x 128] into smem[0..64KB), 16B swizzle (row&7).
        const float* Eg = Enc + (size_t)bm * EDIM + bn;
        #pragma unroll
        for (int i = 0; i < 16; i++) {
            const int id  = tid + i * 256;
            const int row = id >> 5, ch = id & 31;
            const uint32_t off = (uint32_t)(row * 512 + ((ch ^ (row & 7)) << 4));
            cp16(sbase + off, Eg + (size_t)row * EDIM + ch * 4);
        }
        asm volatile("cp.async.commit_group;" ::: "memory");
        asm volatile("cp.async.wait_group 0;" ::: "memory");
        __syncthreads();

        // Phase A: per-column max (sentinel -1e30)
        float M[8];
        #pragma unroll
        for (int ci = 0; ci < 8; ci++) M[ci] = -1e30f;
        #pragma unroll
        for (int mt = 0; mt < 4; mt++)
            #pragma unroll
            for (int rp = 0; rp < 2; rp++) {
                const int lr = wm + mt * 16 + gp + rp * 8;
                const bool valid = (l0 + lr) < len;
                #pragma unroll
                for (int nt = 0; nt < 4; nt++)
                    #pragma unroll
                    for (int j = 0; j < 2; j++) {
                        const float x = valid ? acc[mt][nt][rp * 2 + j] : -1e30f;
                        M[nt * 2 + j] = fmaxf(M[nt * 2 + j], x);
                    }
            }
        #pragma unroll
        for (int ci = 0; ci < 8; ci++) {
            M[ci] = fmaxf(M[ci], __shfl_xor_sync(0xFFFFFFFFu, M[ci], 4));
            M[ci] = fmaxf(M[ci], __shfl_xor_sync(0xFFFFFFFFu, M[ci], 8));
            M[ci] = fmaxf(M[ci], __shfl_xor_sync(0xFFFFFFFFu, M[ci], 16));
        }
        float* smax = reinterpret_cast<float*>(smem + 4 * STB);  // [8][32]
        if (gp == 0) {
            #pragma unroll
            for (int ci = 0; ci < 8; ci++) {
                const int col = (ci >> 1) * 8 + tg * 2 + (ci & 1);
                smax[wid * 32 + col] = M[ci];
            }
        }
        __syncthreads();
        #pragma unroll
        for (int ci = 0; ci < 8; ci++) {
            const int col = (ci >> 1) * 8 + tg * 2 + (ci & 1);
            M[ci] = fmaxf(M[ci], smax[(wid ^ 4) * 32 + col]);
        }

        // Phase B: Σ exp(x-M), Σ exp(x-M)·enc
        float S[8], Aa[8];
        #pragma unroll
        for (int ci = 0; ci < 8; ci++) { S[ci] = 0.0f; Aa[ci] = 0.0f; }
        #pragma unroll
        for (int mt = 0; mt < 4; mt++)
            #pragma unroll
            for (int rp = 0; rp < 2; rp++) {
                const int lr = wm + mt * 16 + gp + rp * 8;
                const bool valid = (l0 + lr) < len;
                #pragma unroll
                for (int nt = 0; nt < 4; nt++) {
                    const int n0 = wn + nt * 8 + tg * 2;
                    const uint32_t eoff = (uint32_t)(lr * 512 +
                        (((n0 >> 2) ^ (lr & 7)) << 4) + (n0 & 3) * 4);
                    const float2 ev =
                        *reinterpret_cast<const float2*>(smem + eoff);
                    #pragma unroll
                    for (int j = 0; j < 2; j++) {
                        const float x = valid ? acc[mt][nt][rp * 2 + j] : -1e30f;
                        const float p = __expf(x - M[nt * 2 + j]);
                        S [nt * 2 + j] += p;
                        Aa[nt * 2 + j] += p * (j ? ev.y : ev.x);
                    }
                }
            }
        #pragma unroll
        for (int ci = 0; ci < 8; ci++) {
            #pragma unroll
            for (int msk = 4; msk <= 16; msk <<= 1) {
                S [ci] += __shfl_xor_sync(0xFFFFFFFFu, S [ci], msk);
                Aa[ci] += __shfl_xor_sync(0xFFFFFFFFu, Aa[ci], msk);
            }
        }
        float* ssum = smax + 256;   // [4 warps][32 cols][2]
        if (wid < 4 && gp == 0) {
            #pragma unroll
            for (int ci = 0; ci < 8; ci++) {
                const int col = (ci >> 1) * 8 + tg * 2 + (ci & 1);
                ssum[(wid * 32 + col) * 2 + 0] = S[ci];
                ssum[(wid * 32 + col) * 2 + 1] = Aa[ci];
            }
        }
        __syncthreads();
        if (wid >= 4 && gp == 0) {
            const size_t base = ((size_t)batch * NCH2 + chunk) * EDIM + bn + wn;
            #pragma unroll
            for (int ci = 0; ci < 8; ci++) {
                const int col = (ci >> 1) * 8 + tg * 2 + (ci & 1);
                pm[base + col] = M[ci];
                ps[base + col] = S[ci]  + ssum[((wid - 4) * 32 + col) * 2 + 0];
                pa[base + col] = Aa[ci] + ssum[((wid - 4) * 32 + col) * 2 + 1];
            }
        }
    }
}

// ---------------------------------------------------------------------------
// Merge NCH2 partials -> out[b][e].
// ---------------------------------------------------------------------------
__global__ __launch_bounds__(512) void softmax_merge(
    const float* __restrict__ pm, const float* __restrict__ ps,
    const float* __restrict__ pa, float* __restrict__ out)
{
    const int b = blockIdx.x, e = threadIdx.x;
    float M = -1e30f;
    #pragma unroll 4
    for (int c = 0; c < NCH2; c++)
        M = fmaxf(M, pm[((size_t)b * NCH2 + c) * EDIM + e]);
    float S = 0.0f, Acc = 0.0f;
    #pragma unroll 4
    for (int c = 0; c < NCH2; c++) {
        const size_t o = ((size_t)b * NCH2 + c) * EDIM + e;
        const float w = __expf(pm[o] - M);
        S   += ps[o] * w;
        Acc += pa[o] * w;
    }
    out[(size_t)b * EDIM + e] = Acc / S;
}

// ---------------------------------------------------------------------------
// Inputs: encodings [B,L,E] f32, lengths [B] i32, W_h [E,H] f32,
//         b_h [H] f32, W_c [H,E] f32. Output: [B,1,E] f32.
// ---------------------------------------------------------------------------
extern "C" void kernel_launch(void* const* d_in, const int* in_sizes, int n_in,
                              void* d_out, int out_size)
{
    const float* enc = (const float*)d_in[0];
    const int*   len = (const int*)  d_in[1];
    const float* W_h = (const float*)d_in[2];
    const float* b_h = (const float*)d_in[3];
    const float* W_c = (const float*)d_in[4];
    float* out = (float*)d_out;

    __half *encF, *hF, *WhF, *WcF;
    float *pm, *ps, *pa;
    cudaGetSymbolAddress((void**)&encF, g_encF);
    cudaGetSymbolAddress((void**)&hF,   g_hF);
    cudaGetSymbolAddress((void**)&WhF,  g_WhF);
    cudaGetSymbolAddress((void**)&WcF,  g_WcF);
    cudaGetSymbolAddress((void**)&pm,   g_pm);
    cudaGetSymbolAddress((void**)&ps,   g_ps);
    cudaGetSymbolAddress((void**)&pa,   g_pa);

    cudaFuncSetAttribute(gemm_fp16<true>,
        cudaFuncAttributeMaxDynamicSharedMemorySize, GEMM_SMEM);
    cudaFuncSetAttribute(gemm_fp16<false>,
        cudaFuncAttributeMaxDynamicSharedMemorySize, GEMM_SMEM);

    convert_A<<<(MTOT * 64) / 256, 256>>>(enc, encF);
    dim3 gw((512 * 512) / 256, 2);
    convert_W<<<gw, 256>>>(W_h, W_c, WhF, WcF);

    dim3 gg(4, MTOT / 128);   // (N/128, M/128)
    gemm_fp16<true ><<<gg, 256, GEMM_SMEM>>>(
        encF, WhF, b_h, hF, nullptr, nullptr, nullptr, nullptr, nullptr);
    gemm_fp16<false><<<gg, 256, GEMM_SMEM>>>(
        hF, WcF, nullptr, nullptr, enc, len, pm, ps, pa);

    softmax_merge<<<BATCH, EDIM>>>(pm, ps, pa, out);
}

// round 12
// speedup vs baseline: 12.2443x; 1.6071x over previous
#include <cuda_runtime.h>
#include <cuda_fp16.h>
#include <math.h>
#include <stdint.h>

// Problem constants
#define BATCH 32
#define SEQL  2048
#define EDIM  512
#define HDIM  512
#define KDIM  512
#define MTOT  (BATCH * SEQL)     // 65536
#define NCH2  16                 // softmax chunks = 2048/128

// All GEMM operands plain fp16: A row-major [M][512], W N-major [n][512].
__device__ __half g_encF[(size_t)MTOT * 512];
__device__ __half g_hF  [(size_t)MTOT * 512];
__device__ __half g_WhF [(size_t)HDIM * 512];
__device__ __half g_WcF [(size_t)EDIM * 512];
__device__ float g_pm [BATCH * NCH2 * EDIM];
__device__ float g_ps [BATCH * NCH2 * EDIM];
__device__ float g_pa [BATCH * NCH2 * EDIM];

// ---------------------------------------------------------------------------
// helpers
// ---------------------------------------------------------------------------
__device__ __forceinline__ uint32_t s2u(const void* p) {
    uint32_t a;
    asm("{ .reg .u64 t; cvta.to.shared.u64 t, %1; cvt.u32.u64 %0, t; }"
        : "=r"(a) : "l"(p));
    return a;
}
__device__ __forceinline__ void cp16(uint32_t dst, const void* src) {
    asm volatile("cp.async.cg.shared.global [%0], [%1], 16;"
                 :: "r"(dst), "l"(src) : "memory");
}
__device__ __forceinline__ void ldsm4(uint32_t* r, uint32_t addr) {
    asm volatile("ldmatrix.sync.aligned.m8n8.x4.shared.b16 {%0,%1,%2,%3}, [%4];"
                 : "=r"(r[0]), "=r"(r[1]), "=r"(r[2]), "=r"(r[3]) : "r"(addr));
}
__device__ __forceinline__ void mma16816h(float* d, const uint32_t* a,
                                          const uint32_t* b) {
    asm volatile(
        "mma.sync.aligned.m16n8k16.row.col.f32.f16.f16.f32 "
        "{%0,%1,%2,%3},{%4,%5,%6,%7},{%8,%9},{%0,%1,%2,%3};"
        : "+f"(d[0]), "+f"(d[1]), "+f"(d[2]), "+f"(d[3])
        : "r"(a[0]), "r"(a[1]), "r"(a[2]), "r"(a[3]), "r"(b[0]), "r"(b[1]));
}
// fast tanh: (e^{2x}-1)/(e^{2x}+1), clamp avoids inf/inf; err ~1e-6.
__device__ __forceinline__ float fast_tanh(float x) {
    x = fminf(fmaxf(x, -15.0f), 15.0f);
    const float e = __expf(2.0f * x);
    return __fdividef(e - 1.0f, e + 1.0f);
}

// ---------------------------------------------------------------------------
// convert encodings fp32 [M][512] -> plain fp16, skipping rows >= len
// (those rows' h / att contributions are masked to 0 downstream).
// ---------------------------------------------------------------------------
__global__ __launch_bounds__(256) void convert_A(
    const float* __restrict__ src, __half* __restrict__ dst,
    const int* __restrict__ lengths)
{
    const size_t g = (size_t)blockIdx.x * 256 + threadIdx.x;   // M*64 threads
    const int m = (int)(g >> 6);
    if ((m & 2047) >= lengths[m >> 11]) return;
    const int k = (int)(g & 63) * 8;
    const float4 v0 = *reinterpret_cast<const float4*>(src + (size_t)m * KDIM + k);
    const float4 v1 = *reinterpret_cast<const float4*>(src + (size_t)m * KDIM + k + 4);
    __half2 h[4];
    h[0] = __floats2half2_rn(v0.x, v0.y);
    h[1] = __floats2half2_rn(v0.z, v0.w);
    h[2] = __floats2half2_rn(v1.x, v1.y);
    h[3] = __floats2half2_rn(v1.z, v1.w);
    *reinterpret_cast<uint4*>(dst + (size_t)m * 512 + k) =
        *reinterpret_cast<uint4*>(h);
}

// ---------------------------------------------------------------------------
// convert both W fp32 [K][N] -> N-major plain fp16 [n][k].
// ---------------------------------------------------------------------------
__global__ __launch_bounds__(256) void convert_W(
    const float* __restrict__ Wh, const float* __restrict__ Wc,
    __half* __restrict__ dh, __half* __restrict__ dc)
{
    const float* W = blockIdx.y ? Wc : Wh;
    __half* dst = blockIdx.y ? dc : dh;
    const int g = blockIdx.x * 256 + threadIdx.x;   // 512*512 threads
    const int k = g >> 9;
    const int n = g & 511;
    dst[(size_t)n * 512 + k] = __float2half_rn(W[(size_t)k * 512 + n]);
}

// ---------------------------------------------------------------------------
// Single-pass fp16 tensor-core GEMM: C = A[M,512] @ B[n][512]^T.
// CTA tile 128x128, 8 warps (2m x 4n), warp 64x32, k=32/stage,
// 4-stage cp.async pipeline (16KB/stage), fully unrolled, 2 CTAs/SM.
// CTAs whose entire 128-row range is masked (l0 >= len) EXIT EARLY:
//   TANH=true : skip everything (h rows never read downstream).
//   TANH=false: write empty partials (pm=-1e30, ps=pa=0) and exit.
// TANH=true : bias+tanh -> plain fp16 h via smem-staged coalesced stores.
// TANH=false: fused masked-softmax partial epilogue (att never hits DRAM).
// ---------------------------------------------------------------------------
#define STB        16384
#define GEMM_SMEM  (4 * STB + 4096)

template <bool TANH>
__global__ void __launch_bounds__(256, 2) gemm_fp16(
    const __half* __restrict__ A, const __half* __restrict__ Bm,
    const float* __restrict__ bias, __half* __restrict__ Hout,
    const float* __restrict__ Enc, const int* __restrict__ lengths,
    float* __restrict__ pm, float* __restrict__ ps, float* __restrict__ pa)
{
    extern __shared__ char smem[];
    const uint32_t sbase = s2u(smem);
    const int tid  = threadIdx.x;
    const int wid  = tid >> 5, lane = tid & 31;
    const int bm = blockIdx.y * 128, bn = blockIdx.x * 128;
    const int wm = (wid >> 2) * 64, wn = (wid & 3) * 32;

    // Batch / length context (row tiles never straddle batches).
    const int batch = bm >> 11;
    const int l0    = bm & 2047;
    const int len   = lengths[batch];

    // Early exit: this CTA's rows are entirely masked.
    if (l0 >= len) {
        if (!TANH) {
            const int chunk = l0 >> 7;
            const size_t base = ((size_t)batch * NCH2 + chunk) * EDIM + bn;
            for (int c = tid; c < 128; c += 256) {
                pm[base + c] = -1e30f;
                ps[base + c] = 0.0f;
                pa[base + c] = 0.0f;
            }
        }
        return;
    }

    // ldmatrix invariants (64B rows, 4-chunk XOR swizzle keyed by (row>>1)&3)
    const uint32_t xa   = (uint32_t)(((lane & 15) >> 1) & 3);
    const uint32_t rowA = (uint32_t)(wm + (lane & 15)) * 64;
    const int cA0 = (lane >> 4);
    const int cB0 = ((lane >> 3) & 1);
    const uint32_t laneR = (uint32_t)((lane & 7) + ((lane >> 4) & 1) * 8);
    const uint32_t xb    = (laneR >> 1) & 3;
    const uint32_t rowB  = (uint32_t)(wn + (int)laneR) * 64;

    float acc[4][4][4];
    #pragma unroll
    for (int i = 0; i < 4; i++)
        #pragma unroll
        for (int j = 0; j < 4; j++)
            #pragma unroll
            for (int q = 0; q < 4; q++) acc[i][j][q] = 0.0f;

    // cp.async invariants: A/B each 512 16B-chunks (128 rows x 4), 2/thread.
    const int arow = tid >> 2, ac = tid & 3;
    const __half* Ag = A  + (size_t)(bm + arow) * 512 + ac * 8;
    const __half* Bg = Bm + (size_t)(bn + arow) * 512 + ac * 8;
    const uint32_t soff = (uint32_t)(arow * 64 + ((ac ^ ((arow >> 1) & 3)) << 4));

    auto load_stage = [&](int kc, int buf) {
        const uint32_t sA = sbase + (uint32_t)buf * STB;
        const uint32_t sB = sA + 8192;
        cp16(sA + soff,        Ag + kc * 32);
        cp16(sA + soff + 4096, Ag + (size_t)64 * 512 + kc * 32);
        cp16(sB + soff,        Bg + kc * 32);
        cp16(sB + soff + 4096, Bg + (size_t)64 * 512 + kc * 32);
    };

    auto compute_stage = [&](int buf) {
        const uint32_t sA = sbase + (uint32_t)buf * STB;
        const uint32_t sB = sA + 8192;
        #pragma unroll
        for (int s = 0; s < 2; s++) {
            const uint32_t ca = (uint32_t)(s * 2 + cA0);
            const uint32_t cb = (uint32_t)(s * 2 + cB0);
            uint32_t aF[4][4];
            #pragma unroll
            for (int mt = 0; mt < 4; mt++)
                ldsm4(aF[mt], sA + rowA + mt * 1024 + ((ca ^ xa) << 4));
            uint32_t bF[4][2];
            #pragma unroll
            for (int np = 0; np < 2; np++) {
                uint32_t t[4];
                ldsm4(t, sB + rowB + np * 1024 + ((cb ^ xb) << 4));
                bF[np * 2 + 0][0] = t[0]; bF[np * 2 + 0][1] = t[1];
                bF[np * 2 + 1][0] = t[2]; bF[np * 2 + 1][1] = t[3];
            }
            #pragma unroll
            for (int mt = 0; mt < 4; mt++)
                #pragma unroll
                for (int nt = 0; nt < 4; nt++)
                    mma16816h(acc[mt][nt], aF[mt], bF[nt]);
        }
    };

    // 4-stage pipeline, fully unrolled.
    load_stage(0, 0);
    asm volatile("cp.async.commit_group;" ::: "memory");
    load_stage(1, 1);
    asm volatile("cp.async.commit_group;" ::: "memory");
    load_stage(2, 2);
    asm volatile("cp.async.commit_group;" ::: "memory");

    #pragma unroll
    for (int kc = 0; kc < 16; kc++) {
        asm volatile("cp.async.wait_group 2;" ::: "memory");
        __syncthreads();            // stage kc visible; stage (kc+3)&3 free
        if (kc + 3 < 16)
            load_stage(kc + 3, (kc + 3) & 3);
        asm volatile("cp.async.commit_group;" ::: "memory");
        compute_stage(kc & 3);
    }

    const int gp = lane >> 2, tg = lane & 3;

    if (TANH) {
        // --- GEMM1 epilogue: bias+tanh -> fp16, smem-staged coalesced out ---
        __syncthreads();   // drain pipeline readers before smem reuse
        #pragma unroll
        for (int mt = 0; mt < 4; mt++) {
            #pragma unroll
            for (int nt = 0; nt < 4; nt++) {
                const int ln = wn + nt * 8 + tg * 2;
                const float b0 = __ldg(bias + bn + ln);
                const float b1 = __ldg(bias + bn + ln + 1);
                #pragma unroll
                for (int rp = 0; rp < 2; rp++) {
                    const int r = wm + mt * 16 + gp + rp * 8;
                    const float d0 = fast_tanh(acc[mt][nt][rp * 2 + 0] + b0);
                    const float d1 = fast_tanh(acc[mt][nt][rp * 2 + 1] + b1);
                    const __half2 hp = __floats2half2_rn(d0, d1);
                    const uint32_t sw = (uint32_t)((ln >> 3) ^ (r & 15));
                    *reinterpret_cast<__half2*>(
                        smem + r * 256 + (sw << 4) + (ln & 7) * 2) = hp;
                }
            }
        }
        __syncthreads();
        __half* dsth = Hout + (size_t)bm * 512 + bn;
        #pragma unroll
        for (int i = 0; i < 8; i++) {
            const int id  = tid + i * 256;        // 0..2047
            const int row = id >> 4;
            const int c   = id & 15;
            const uint32_t sw = (uint32_t)(c ^ (row & 15));
            const uint4 v = *reinterpret_cast<uint4*>(smem + row * 256 + (sw << 4));
            *reinterpret_cast<uint4*>(dsth + (size_t)row * 512 + c * 8) = v;
        }
    } else {
        // --- GEMM2 fused epilogue: masked softmax partials over 128 rows ---
        const int chunk = l0 >> 7;

        __syncthreads();   // drain pipeline readers before smem reuse

        // enc fp32 tile [128 x 128] into smem[0..64KB), 16B swizzle (row&7).
        const float* Eg = Enc + (size_t)bm * EDIM + bn;
        #pragma unroll
        for (int i = 0; i < 16; i++) {
            const int id  = tid + i * 256;
            const int row = id >> 5, ch = id & 31;
            const uint32_t off = (uint32_t)(row * 512 + ((ch ^ (row & 7)) << 4));
            cp16(sbase + off, Eg + (size_t)row * EDIM + ch * 4);
        }
        asm volatile("cp.async.commit_group;" ::: "memory");
        asm volatile("cp.async.wait_group 0;" ::: "memory");
        __syncthreads();

        // Phase A: per-column max (sentinel -1e30)
        float M[8];
        #pragma unroll
        for (int ci = 0; ci < 8; ci++) M[ci] = -1e30f;
        #pragma unroll
        for (int mt = 0; mt < 4; mt++)
            #pragma unroll
            for (int rp = 0; rp < 2; rp++) {
                const int lr = wm + mt * 16 + gp + rp * 8;
                const bool valid = (l0 + lr) < len;
                #pragma unroll
                for (int nt = 0; nt < 4; nt++)
                    #pragma unroll
                    for (int j = 0; j < 2; j++) {
                        const float x = valid ? acc[mt][nt][rp * 2 + j] : -1e30f;
                        M[nt * 2 + j] = fmaxf(M[nt * 2 + j], x);
                    }
            }
        #pragma unroll
        for (int ci = 0; ci < 8; ci++) {
            M[ci] = fmaxf(M[ci], __shfl_xor_sync(0xFFFFFFFFu, M[ci], 4));
            M[ci] = fmaxf(M[ci], __shfl_xor_sync(0xFFFFFFFFu, M[ci], 8));
            M[ci] = fmaxf(M[ci], __shfl_xor_sync(0xFFFFFFFFu, M[ci], 16));
        }
        float* smax = reinterpret_cast<float*>(smem + 4 * STB);  // [8][32]
        if (gp == 0) {
            #pragma unroll
            for (int ci = 0; ci < 8; ci++) {
                const int col = (ci >> 1) * 8 + tg * 2 + (ci & 1);
                smax[wid * 32 + col] = M[ci];
            }
        }
        __syncthreads();
        #pragma unroll
        for (int ci = 0; ci < 8; ci++) {
            const int col = (ci >> 1) * 8 + tg * 2 + (ci & 1);
            M[ci] = fmaxf(M[ci], smax[(wid ^ 4) * 32 + col]);
        }

        // Phase B: Σ exp(x-M), Σ exp(x-M)·enc
        float S[8], Aa[8];
        #pragma unroll
        for (int ci = 0; ci < 8; ci++) { S[ci] = 0.0f; Aa[ci] = 0.0f; }
        #pragma unroll
        for (int mt = 0; mt < 4; mt++)
            #pragma unroll
            for (int rp = 0; rp < 2; rp++) {
                const int lr = wm + mt * 16 + gp + rp * 8;
                const bool valid = (l0 + lr) < len;
                #pragma unroll
                for (int nt = 0; nt < 4; nt++) {
                    const int n0 = wn + nt * 8 + tg * 2;
                    const uint32_t eoff = (uint32_t)(lr * 512 +
                        (((n0 >> 2) ^ (lr & 7)) << 4) + (n0 & 3) * 4);
                    const float2 ev =
                        *reinterpret_cast<const float2*>(smem + eoff);
                    #pragma unroll
                    for (int j = 0; j < 2; j++) {
                        const float x = valid ? acc[mt][nt][rp * 2 + j] : -1e30f;
                        const float p = __expf(x - M[nt * 2 + j]);
                        S [nt * 2 + j] += p;
                        Aa[nt * 2 + j] += p * (j ? ev.y : ev.x);
                    }
                }
            }
        #pragma unroll
        for (int ci = 0; ci < 8; ci++) {
            #pragma unroll
            for (int msk = 4; msk <= 16; msk <<= 1) {
                S [ci] += __shfl_xor_sync(0xFFFFFFFFu, S [ci], msk);
                Aa[ci] += __shfl_xor_sync(0xFFFFFFFFu, Aa[ci], msk);
            }
        }
        float* ssum = smax + 256;   // [4 warps][32 cols][2]
        if (wid < 4 && gp == 0) {
            #pragma unroll
            for (int ci = 0; ci < 8; ci++) {
                const int col = (ci >> 1) * 8 + tg * 2 + (ci & 1);
                ssum[(wid * 32 + col) * 2 + 0] = S[ci];
                ssum[(wid * 32 + col) * 2 + 1] = Aa[ci];
            }
        }
        __syncthreads();
        if (wid >= 4 && gp == 0) {
            const size_t base = ((size_t)batch * NCH2 + chunk) * EDIM + bn + wn;
            #pragma unroll
            for (int ci = 0; ci < 8; ci++) {
                const int col = (ci >> 1) * 8 + tg * 2 + (ci & 1);
                pm[base + col] = M[ci];
                ps[base + col] = S[ci]  + ssum[((wid - 4) * 32 + col) * 2 + 0];
                pa[base + col] = Aa[ci] + ssum[((wid - 4) * 32 + col) * 2 + 1];
            }
        }
    }
}

// ---------------------------------------------------------------------------
// Merge NCH2 partials -> out[b][e].
// ---------------------------------------------------------------------------
__global__ __launch_bounds__(512) void softmax_merge(
    const float* __restrict__ pm, const float* __restrict__ ps,
    const float* __restrict__ pa, float* __restrict__ out)
{
    const int b = blockIdx.x, e = threadIdx.x;
    float M = -1e30f;
    #pragma unroll 4
    for (int c = 0; c < NCH2; c++)
        M = fmaxf(M, pm[((size_t)b * NCH2 + c) * EDIM + e]);
    float S = 0.0f, Acc = 0.0f;
    #pragma unroll 4
    for (int c = 0; c < NCH2; c++) {
        const size_t o = ((size_t)b * NCH2 + c) * EDIM + e;
        const float w = __expf(pm[o] - M);
        S   += ps[o] * w;
        Acc += pa[o] * w;
    }
    out[(size_t)b * EDIM + e] = Acc / S;
}

// ---------------------------------------------------------------------------
// Inputs: encodings [B,L,E] f32, lengths [B] i32, W_h [E,H] f32,
//         b_h [H] f32, W_c [H,E] f32. Output: [B,1,E] f32.
// ---------------------------------------------------------------------------
extern "C" void kernel_launch(void* const* d_in, const int* in_sizes, int n_in,
                              void* d_out, int out_size)
{
    const float* enc = (const float*)d_in[0];
    const int*   len = (const int*)  d_in[1];
    const float* W_h = (const float*)d_in[2];
    const float* b_h = (const float*)d_in[3];
    const float* W_c = (const float*)d_in[4];
    float* out = (float*)d_out;

    __half *encF, *hF, *WhF, *WcF;
    float *pm, *ps, *pa;
    cudaGetSymbolAddress((void**)&encF, g_encF);
    cudaGetSymbolAddress((void**)&hF,   g_hF);
    cudaGetSymbolAddress((void**)&WhF,  g_WhF);
    cudaGetSymbolAddress((void**)&WcF,  g_WcF);
    cudaGetSymbolAddress((void**)&pm,   g_pm);
    cudaGetSymbolAddress((void**)&ps,   g_ps);
    cudaGetSymbolAddress((void**)&pa,   g_pa);

    cudaFuncSetAttribute(gemm_fp16<true>,
        cudaFuncAttributeMaxDynamicSharedMemorySize, GEMM_SMEM);
    cudaFuncSetAttribute(gemm_fp16<false>,
        cudaFuncAttributeMaxDynamicSharedMemorySize, GEMM_SMEM);

    convert_A<<<(MTOT * 64) / 256, 256>>>(enc, encF, len);
    dim3 gw((512 * 512) / 256, 2);
    convert_W<<<gw, 256>>>(W_h, W_c, WhF, WcF);

    dim3 gg(4, MTOT / 128);   // (N/128, M/128)
    gemm_fp16<true ><<<gg, 256, GEMM_SMEM>>>(
        encF, WhF, b_h, hF, nullptr, len, nullptr, nullptr, nullptr);
    gemm_fp16<false><<<gg, 256, GEMM_SMEM>>>(
        hF, WcF, nullptr, nullptr, enc, len, pm, ps, pa);

    softmax_merge<<<BATCH, EDIM>>>(pm, ps, pa, out);
}